// round 2
// baseline (speedup 1.0000x reference)
#include <cuda_runtime.h>
#include <math_constants.h>

#define NN 10000
#define BB 4
#define EE 160000
#define CC 64
#define CE 16
#define NR (NN*BB)          // 40000 rows

// ---------------- scratch (device globals; allocation-free) ----------------
// xp / gate / aggr use an INTERLEAVED channel layout: element for channel c of
// row r lives at [r*64 + (c&31)*2 + (c>>5)], i.e. channels (c, c+32) adjacent.
__device__ float g_xp[NR*CC];
__device__ float g_y1[NR*CC];        // layer-1 output (natural layout)
__device__ float g_asrc[NR];         // xp . (q @ aw_q)
__device__ float g_adst[NR];         // xp . (k @ aw_k)
__device__ float g_gate[EE*CC];      // sigmoid(edge_attr @ w_e), interleaved
__device__ float g_escal[EE];        // edge_attr . (w_e @ aw_e) + ab
__device__ float g_aggr[NR*CC];      // segment-max result, interleaved
__device__ float g_qaw[CC], g_kaw[CC], g_wea[CE];
__device__ float g_abv;
// CSR by destination (built once per launch; edge_index shared by both layers)
__device__ int  g_deg[NN];
__device__ int  g_off[NN+1];
__device__ int  g_cur[NN];
__device__ int2 g_lst[EE];           // {edge id, src node}

__device__ __forceinline__ float sigmoidf(float x) {
    return 1.0f / (1.0f + __expf(-x));
}
__device__ __forceinline__ int ilv(int c) { return (c & 31) * 2 + (c >> 5); }

// ---------------- CSR build ------------------------------------------------
__global__ void zero_deg_kernel() {
    int i = blockIdx.x * 256 + threadIdx.x;
    if (i < NN) g_deg[i] = 0;
}
__global__ void count_kernel(const int* __restrict__ ei) {
    int e = blockIdx.x * 256 + threadIdx.x;
    if (e < EE) atomicAdd(&g_deg[ei[EE + e]], 1);
}
__global__ void scan_kernel() {
    __shared__ int s[1024];
    const int CH = (NN + 1023) / 1024;  // 10
    int t = threadIdx.x;
    int base = t * CH;
    int local[CH];
    int sum = 0;
    #pragma unroll
    for (int i = 0; i < CH; i++) {
        local[i] = sum;
        if (base + i < NN) sum += g_deg[base + i];
    }
    s[t] = sum;
    __syncthreads();
    for (int off = 1; off < 1024; off <<= 1) {
        int v = (t >= off) ? s[t - off] : 0;
        __syncthreads();
        s[t] += v;
        __syncthreads();
    }
    int excl = (t == 0) ? 0 : s[t - 1];
    #pragma unroll
    for (int i = 0; i < CH; i++) {
        if (base + i < NN) {
            int o = excl + local[i];
            g_off[base + i] = o;
            g_cur[base + i] = o;
        }
    }
    if (t == 1023) g_off[NN] = s[1023];
}
__global__ void scatter_kernel(const int* __restrict__ ei) {
    int e = blockIdx.x * 256 + threadIdx.x;
    if (e < EE) {
        int src = ei[e];
        int dst = ei[EE + e];
        int pos = atomicAdd(&g_cur[dst], 1);
        g_lst[pos] = make_int2(e, src);
    }
}

// ---------------- prep: fold attention weights ----------------------------
__global__ void prep_kernel(const float* __restrict__ q, const float* __restrict__ k,
                            const float* __restrict__ aw, const float* __restrict__ ab,
                            const float* __restrict__ we) {
    int t = threadIdx.x;  // 64 threads
    float sq = 0.f, sk = 0.f;
    for (int c = 0; c < CC; c++) {
        sq += q[t*CC + c] * aw[c];
        sk += k[t*CC + c] * aw[CC + c];
    }
    g_qaw[t] = sq;
    g_kaw[t] = sk;
    if (t < CE) {
        float s = 0.f;
        for (int c = 0; c < CC; c++) s += we[t*CC + c] * aw[2*CC + c];
        g_wea[t] = s;
    }
    if (t == 0) g_abv = ab[0];
}

// ---------------- node transform: xp = x @ w_n + att scalars ---------------
// block = 512 threads = 8 rows x 64 channels
__global__ void node_xform_kernel(const float* __restrict__ x, const float* __restrict__ wn) {
    __shared__ float ws[CC*CC];
    __shared__ float xs[8*CC];
    __shared__ float wq[16], wk[16];
    int tid = threadIdx.x;
    for (int i = tid; i < CC*CC; i += 512) ws[i] = wn[i];
    int row0 = blockIdx.x * 8;
    int r = tid >> 6, c = tid & 63;
    int row = row0 + r;
    xs[tid] = x[row*CC + c];
    __syncthreads();
    float acc = 0.f;
    #pragma unroll
    for (int kk = 0; kk < CC; kk++) acc += xs[r*CC + kk] * ws[kk*CC + c];
    g_xp[row*CC + ilv(c)] = acc;                  // interleaved store
    float pq = acc * g_qaw[c];
    float pk = acc * g_kaw[c];
    #pragma unroll
    for (int o = 16; o; o >>= 1) {
        pq += __shfl_down_sync(0xffffffffu, pq, o);
        pk += __shfl_down_sync(0xffffffffu, pk, o);
    }
    int w = tid >> 5;
    if ((tid & 31) == 0) { wq[w] = pq; wk[w] = pk; }
    __syncthreads();
    if (tid < 8) {
        g_asrc[row0 + tid] = wq[2*tid] + wq[2*tid + 1];
        g_adst[row0 + tid] = wk[2*tid] + wk[2*tid + 1];
    }
}

// ---------------- edge gate: gate = sigmoid(edge_attr @ w_e), e_scal -------
// one warp per edge, block = 256 (8 edges)
__global__ void edge_gate_kernel(const float* __restrict__ eattr, const float* __restrict__ we) {
    __shared__ float wes[CE*CC];
    __shared__ float weas[CE];
    int tid = threadIdx.x;
    for (int i = tid; i < CE*CC; i += 256) wes[i] = we[i];
    if (tid < CE) weas[tid] = g_wea[tid];
    __syncthreads();
    int e = blockIdx.x * 8 + (tid >> 5);
    int lane = tid & 31;
    float av = (lane < CE) ? eattr[e*CE + lane] : 0.f;
    float acc1 = 0.f, acc2 = 0.f;
    #pragma unroll
    for (int j = 0; j < CE; j++) {
        float aj = __shfl_sync(0xffffffffu, av, j);
        acc1 += aj * wes[j*CC + lane];
        acc2 += aj * wes[j*CC + 32 + lane];
    }
    float sc = (lane < CE) ? av * weas[lane] : 0.f;
    #pragma unroll
    for (int o = 16; o; o >>= 1) sc += __shfl_down_sync(0xffffffffu, sc, o);
    // interleaved store: channels (lane, lane+32) adjacent
    *(float2*)&g_gate[e*CC + lane*2] = make_float2(sigmoidf(acc1), sigmoidf(acc2));
    if (lane == 0) g_escal[e] = sc + g_abv;
}

// ---------------- segment max over CSR: one warp per node ------------------
// block = 256 (8 nodes)
__global__ void node_aggr_kernel() {
    int n = blockIdx.x * 8 + (threadIdx.x >> 5);
    int lane = threadIdx.x & 31;
    int beg = g_off[n], end = g_off[n+1];
    float4 ad = *(const float4*)&g_adst[n*4];
    float mx0[BB], mx1[BB];
    #pragma unroll
    for (int b = 0; b < BB; b++) { mx0[b] = -CUDART_INF_F; mx1[b] = -CUDART_INF_F; }
    for (int i = beg; i < end; i++) {
        int2 es = g_lst[i];
        int e = es.x, src = es.y;
        float2 g = *(const float2*)&g_gate[e*CC + lane*2];
        float esc = g_escal[e];
        float4 as = *(const float4*)&g_asrc[src*4];
        float att[BB];
        att[0] = sigmoidf(as.x + ad.x + esc);
        att[1] = sigmoidf(as.y + ad.y + esc);
        att[2] = sigmoidf(as.z + ad.z + esc);
        att[3] = sigmoidf(as.w + ad.w + esc);
        #pragma unroll
        for (int b = 0; b < BB; b++) {
            float2 x = *(const float2*)&g_xp[(src*BB + b)*CC + lane*2];
            mx0[b] = fmaxf(mx0[b], att[b] * x.x * g.x);
            mx1[b] = fmaxf(mx1[b], att[b] * x.y * g.y);
        }
    }
    bool empty = (beg == end);
    #pragma unroll
    for (int b = 0; b < BB; b++) {
        float2 o = empty ? make_float2(0.f, 0.f) : make_float2(mx0[b], mx1[b]);
        *(float2*)&g_aggr[(n*BB + b)*CC + lane*2] = o;
    }
}

// ---------------- output: y = leaky(xp + [xp,aggr]@ow + ob) -----------------
// block = 512 = 8 rows x 64 channels
__global__ void node_out_kernel(const float* __restrict__ ow, const float* __restrict__ ob,
                                float* __restrict__ yout) {
    __shared__ float ows[2*CC*CC];
    __shared__ float xs[8*CC];
    __shared__ float as_[8*CC];
    int tid = threadIdx.x;
    for (int i = tid; i < 2*CC*CC; i += 512) ows[i] = ow[i];
    int row0 = blockIdx.x * 8;
    int r = tid >> 6, c = tid & 63;
    int row = row0 + r;
    float xv = g_xp[row*CC + ilv(c)];
    xs[tid] = xv;
    as_[tid] = g_aggr[row*CC + ilv(c)];
    __syncthreads();
    float acc = ob[c];
    #pragma unroll
    for (int kk = 0; kk < CC; kk++) acc += xs[r*CC + kk] * ows[kk*CC + c];
    #pragma unroll
    for (int kk = 0; kk < CC; kk++) acc += as_[r*CC + kk] * ows[(CC + kk)*CC + c];
    float v = xv + acc;
    yout[row*CC + c] = (v > 0.f) ? v : 0.01f * v;
}

// ---------------- host orchestration ---------------------------------------
static void run_layer(const float* x, const float* ea,
                      const float* wn, const float* we, const float* q,
                      const float* k, const float* aw, const float* ab,
                      const float* ow, const float* ob, float* yout) {
    prep_kernel<<<1, 64>>>(q, k, aw, ab, we);
    node_xform_kernel<<<NR/8, 512>>>(x, wn);
    edge_gate_kernel<<<EE/8, 256>>>(ea, we);
    node_aggr_kernel<<<NN/8, 256>>>();
    node_out_kernel<<<NR/8, 512>>>(ow, ob, yout);
}

extern "C" void kernel_launch(void* const* d_in, const int* in_sizes, int n_in,
                              void* d_out, int out_size) {
    const float* X   = (const float*)d_in[0];
    const int*   ei  = (const int*)  d_in[1];
    const float* ea  = (const float*)d_in[2];
    const float* wn1 = (const float*)d_in[3];
    const float* we1 = (const float*)d_in[4];
    const float* q1  = (const float*)d_in[5];
    const float* k1  = (const float*)d_in[6];
    const float* aw1 = (const float*)d_in[7];
    const float* ab1 = (const float*)d_in[8];
    const float* ow1 = (const float*)d_in[9];
    const float* ob1 = (const float*)d_in[10];
    const float* wn2 = (const float*)d_in[11];
    const float* we2 = (const float*)d_in[12];
    const float* q2  = (const float*)d_in[13];
    const float* k2  = (const float*)d_in[14];
    const float* aw2 = (const float*)d_in[15];
    const float* ab2 = (const float*)d_in[16];
    const float* ow2 = (const float*)d_in[17];
    const float* ob2 = (const float*)d_in[18];

    // CSR build — edge_index identical for both layers, build once
    zero_deg_kernel<<<(NN + 255)/256, 256>>>();
    count_kernel<<<(EE + 255)/256, 256>>>(ei);
    scan_kernel<<<1, 1024>>>();
    scatter_kernel<<<(EE + 255)/256, 256>>>(ei);

    float* y1 = nullptr;
    cudaGetSymbolAddress((void**)&y1, g_y1);

    run_layer(X,  ea, wn1, we1, q1, k1, aw1, ab1, ow1, ob1, y1);
    run_layer(y1, ea, wn2, we2, q2, k2, aw2, ab2, ow2, ob2, (float*)d_out);
}

// round 3
// speedup vs baseline: 1.1025x; 1.1025x over previous
#include <cuda_runtime.h>
#include <math_constants.h>

#define NN 10000
#define BB 4
#define EE 160000
#define CC 64
#define CE 16
#define NR (NN*BB)          // 40000 rows

// ---------------- scratch (device globals; allocation-free) ----------------
// xp / aggr use INTERLEAVED channel layout: channel c of row r lives at
// [r*64 + (c&31)*2 + (c>>5)]  (channels (c, c+32) adjacent -> float2 per lane)
__device__ float g_xp1[NR*CC];
__device__ float g_xp2[NR*CC];
__device__ float g_aggr[NR*CC];
__device__ float g_asrc1[NR], g_adst1[NR];
__device__ float g_asrc2[NR], g_adst2[NR];
__device__ float g_qaw[2][CC], g_kaw[2][CC], g_wea[2][CE];
__device__ float g_abv[2];
// CSR by destination (edge_index shared by both layers)
__device__ int  g_deg[NN];
__device__ int  g_off[NN+1];
__device__ int  g_cur[NN];
__device__ int2 g_lst[EE];           // {edge id, src node}

__device__ __forceinline__ float sigmoidf(float x) {
    return 1.0f / (1.0f + __expf(-x));
}
__device__ __forceinline__ int ilv(int c) { return (c & 31) * 2 + (c >> 5); }

// ---------------- prep: fold attention weights (both layers) + zero deg ----
// grid = 42: block 0 -> layer1 weights, block 1 -> layer2, blocks 2..41 zero deg
__global__ void prep_both_kernel(const float* q1, const float* k1, const float* aw1,
                                 const float* ab1, const float* we1,
                                 const float* q2, const float* k2, const float* aw2,
                                 const float* ab2, const float* we2) {
    int tid = threadIdx.x;
    if (blockIdx.x >= 2) {
        int i = (blockIdx.x - 2) * 256 + tid;
        if (i < NN) g_deg[i] = 0;
        return;
    }
    int layer = blockIdx.x;
    const float* q  = layer ? q2  : q1;
    const float* k  = layer ? k2  : k1;
    const float* aw = layer ? aw2 : aw1;
    const float* ab = layer ? ab2 : ab1;
    const float* we = layer ? we2 : we1;
    int w = tid >> 5, lane = tid & 31;
    float awq_lo = aw[lane],        awq_hi = aw[32 + lane];
    float awk_lo = aw[64 + lane],   awk_hi = aw[96 + lane];
    float aw3_lo = aw[128 + lane],  aw3_hi = aw[160 + lane];
    #pragma unroll
    for (int i = 0; i < 8; i++) {
        int row = w * 8 + i;
        float sq = q[row*CC + lane] * awq_lo + q[row*CC + 32 + lane] * awq_hi;
        float sk = k[row*CC + lane] * awk_lo + k[row*CC + 32 + lane] * awk_hi;
        #pragma unroll
        for (int o = 16; o; o >>= 1) {
            sq += __shfl_down_sync(0xffffffffu, sq, o);
            sk += __shfl_down_sync(0xffffffffu, sk, o);
        }
        if (lane == 0) { g_qaw[layer][row] = sq; g_kaw[layer][row] = sk; }
    }
    #pragma unroll
    for (int i = 0; i < 2; i++) {
        int row = w * 2 + i;   // 16 rows over 8 warps
        float s = we[row*CC + lane] * aw3_lo + we[row*CC + 32 + lane] * aw3_hi;
        #pragma unroll
        for (int o = 16; o; o >>= 1) s += __shfl_down_sync(0xffffffffu, s, o);
        if (lane == 0) g_wea[layer][row] = s;
    }
    if (tid == 0) g_abv[layer] = ab[0];
}

// ---------------- CSR build -------------------------------------------------
__global__ void count_kernel(const int* __restrict__ ei) {
    int e = blockIdx.x * 256 + threadIdx.x;
    if (e < EE) atomicAdd(&g_deg[ei[EE + e]], 1);
}
__global__ void scan_kernel() {
    __shared__ int s[1024];
    const int CH = (NN + 1023) / 1024;  // 10
    int t = threadIdx.x;
    int base = t * CH;
    int local[CH];
    int sum = 0;
    #pragma unroll
    for (int i = 0; i < CH; i++) {
        local[i] = sum;
        if (base + i < NN) sum += g_deg[base + i];
    }
    s[t] = sum;
    __syncthreads();
    for (int off = 1; off < 1024; off <<= 1) {
        int v = (t >= off) ? s[t - off] : 0;
        __syncthreads();
        s[t] += v;
        __syncthreads();
    }
    int excl = (t == 0) ? 0 : s[t - 1];
    #pragma unroll
    for (int i = 0; i < CH; i++) {
        if (base + i < NN) {
            int o = excl + local[i];
            g_off[base + i] = o;
            g_cur[base + i] = o;
        }
    }
    if (t == 1023) g_off[NN] = s[1023];
}
__global__ void scatter_kernel(const int* __restrict__ ei) {
    int e = blockIdx.x * 256 + threadIdx.x;
    if (e < EE) {
        int src = ei[e];
        int dst = ei[EE + e];
        int pos = atomicAdd(&g_cur[dst], 1);
        g_lst[pos] = make_int2(e, src);
    }
}

// ---------------- layer-1 node transform: xp1 = X @ wn1 + att scalars ------
// block = 512 = 8 rows x 64 channels
__global__ void xform1_kernel(const float* __restrict__ x, const float* __restrict__ wn) {
    __shared__ float ws[CC*CC];
    __shared__ float xs[8*CC];
    __shared__ float wq[16], wk[16];
    int tid = threadIdx.x;
    for (int i = tid; i < CC*CC; i += 512) ws[i] = wn[i];
    int row0 = blockIdx.x * 8;
    int r = tid >> 6, c = tid & 63;
    int row = row0 + r;
    xs[tid] = x[row*CC + c];
    __syncthreads();
    float acc = 0.f;
    #pragma unroll
    for (int kk = 0; kk < CC; kk++) acc += xs[r*CC + kk] * ws[kk*CC + c];
    g_xp1[row*CC + ilv(c)] = acc;
    float pq = acc * g_qaw[0][c];
    float pk = acc * g_kaw[0][c];
    #pragma unroll
    for (int o = 16; o; o >>= 1) {
        pq += __shfl_down_sync(0xffffffffu, pq, o);
        pk += __shfl_down_sync(0xffffffffu, pk, o);
    }
    int w = tid >> 5;
    if ((tid & 31) == 0) { wq[w] = pq; wk[w] = pk; }
    __syncthreads();
    if (tid < 8) {
        g_asrc1[row0 + tid] = wq[2*tid] + wq[2*tid + 1];
        g_adst1[row0 + tid] = wk[2*tid] + wk[2*tid + 1];
    }
}

// ---------------- segment max with INLINE gate: one warp per node ----------
// block = 256 (8 nodes). gate/escal computed on the fly (each edge visited once).
__global__ void aggr_kernel(const float* __restrict__ xp, const float* __restrict__ asrcp,
                            const float* __restrict__ adstp, float* __restrict__ aggrp,
                            const float* __restrict__ we, const float* __restrict__ eattr,
                            int layer) {
    __shared__ float wes[CE*CC];
    __shared__ float weas[CE];
    int tid = threadIdx.x;
    for (int i = tid; i < CE*CC; i += 256) wes[i] = we[i];
    if (tid < CE) weas[tid] = g_wea[layer][tid];
    __syncthreads();
    float abv = g_abv[layer];
    int n = blockIdx.x * 8 + (tid >> 5);
    int lane = tid & 31;
    int beg = g_off[n], end = g_off[n+1];
    float4 ad = *(const float4*)&adstp[n*4];
    float mx0[BB], mx1[BB];
    #pragma unroll
    for (int b = 0; b < BB; b++) { mx0[b] = -CUDART_INF_F; mx1[b] = -CUDART_INF_F; }
    for (int i = beg; i < end; i++) {
        int2 es = g_lst[i];
        int e = es.x, src = es.y;
        float av = eattr[e*CE + (lane & 15)];
        // gate channels (lane, lane+32)
        float acc1 = 0.f, acc2 = 0.f;
        #pragma unroll
        for (int j = 0; j < CE; j++) {
            float aj = __shfl_sync(0xffffffffu, av, j);
            acc1 += aj * wes[j*CC + lane];
            acc2 += aj * wes[j*CC + 32 + lane];
        }
        float gA = sigmoidf(acc1);
        float gB = sigmoidf(acc2);
        // escal (replicated in both 16-lane halves)
        float sc = av * weas[lane & 15];
        sc += __shfl_xor_sync(0xffffffffu, sc, 8);
        sc += __shfl_xor_sync(0xffffffffu, sc, 4);
        sc += __shfl_xor_sync(0xffffffffu, sc, 2);
        sc += __shfl_xor_sync(0xffffffffu, sc, 1);
        float esc = sc + abv;
        float4 as = *(const float4*)&asrcp[src*4];
        float att0 = sigmoidf(as.x + ad.x + esc);
        float att1 = sigmoidf(as.y + ad.y + esc);
        float att2 = sigmoidf(as.z + ad.z + esc);
        float att3 = sigmoidf(as.w + ad.w + esc);
        float attv[BB] = {att0, att1, att2, att3};
        #pragma unroll
        for (int b = 0; b < BB; b++) {
            float2 x = *(const float2*)&xp[(src*BB + b)*CC + lane*2];
            mx0[b] = fmaxf(mx0[b], attv[b] * x.x * gA);
            mx1[b] = fmaxf(mx1[b], attv[b] * x.y * gB);
        }
    }
    bool empty = (beg == end);
    #pragma unroll
    for (int b = 0; b < BB; b++) {
        float2 o = empty ? make_float2(0.f, 0.f) : make_float2(mx0[b], mx1[b]);
        *(float2*)&aggrp[(n*BB + b)*CC + lane*2] = o;
    }
}

// ---------------- fused: layer1 output + layer2 transform -------------------
// y1 = leaky(xp1 + [xp1,aggr]@ow1 + ob1); xp2 = y1 @ wn2; asrc2/adst2
// block = 512 = 8 rows x 64 channels
__global__ void mid_kernel(const float* __restrict__ ow, const float* __restrict__ ob,
                           const float* __restrict__ wn2) {
    __shared__ float ows[2*CC*CC];   // 32 KB
    __shared__ float wns[CC*CC];     // 16 KB
    __shared__ float xs[8*CC];
    __shared__ float as_[8*CC];
    __shared__ float ys[8*CC];
    __shared__ float wq[16], wk[16];
    int tid = threadIdx.x;
    for (int i = tid; i < 2*CC*CC; i += 512) ows[i] = ow[i];
    for (int i = tid; i < CC*CC; i += 512)  wns[i] = wn2[i];
    int row0 = blockIdx.x * 8;
    int r = tid >> 6, c = tid & 63;
    int row = row0 + r;
    float xv = g_xp1[row*CC + ilv(c)];
    xs[r*CC + c]  = xv;
    as_[r*CC + c] = g_aggr[row*CC + ilv(c)];
    __syncthreads();
    float acc = ob[c];
    #pragma unroll
    for (int kk = 0; kk < CC; kk++) acc += xs[r*CC + kk] * ows[kk*CC + c];
    #pragma unroll
    for (int kk = 0; kk < CC; kk++) acc += as_[r*CC + kk] * ows[(CC + kk)*CC + c];
    float v = xv + acc;
    v = (v > 0.f) ? v : 0.01f * v;
    ys[r*CC + c] = v;
    __syncthreads();
    float a2 = 0.f;
    #pragma unroll
    for (int kk = 0; kk < CC; kk++) a2 += ys[r*CC + kk] * wns[kk*CC + c];
    g_xp2[row*CC + ilv(c)] = a2;
    float pq = a2 * g_qaw[1][c];
    float pk = a2 * g_kaw[1][c];
    #pragma unroll
    for (int o = 16; o; o >>= 1) {
        pq += __shfl_down_sync(0xffffffffu, pq, o);
        pk += __shfl_down_sync(0xffffffffu, pk, o);
    }
    int w = tid >> 5;
    if ((tid & 31) == 0) { wq[w] = pq; wk[w] = pk; }
    __syncthreads();
    if (tid < 8) {
        g_asrc2[row0 + tid] = wq[2*tid] + wq[2*tid + 1];
        g_adst2[row0 + tid] = wk[2*tid] + wk[2*tid + 1];
    }
}

// ---------------- final output ----------------------------------------------
__global__ void out2_kernel(const float* __restrict__ ow, const float* __restrict__ ob,
                            float* __restrict__ yout) {
    __shared__ float ows[2*CC*CC];
    __shared__ float xs[8*CC];
    __shared__ float as_[8*CC];
    int tid = threadIdx.x;
    for (int i = tid; i < 2*CC*CC; i += 512) ows[i] = ow[i];
    int row0 = blockIdx.x * 8;
    int r = tid >> 6, c = tid & 63;
    int row = row0 + r;
    float xv = g_xp2[row*CC + ilv(c)];
    xs[r*CC + c]  = xv;
    as_[r*CC + c] = g_aggr[row*CC + ilv(c)];
    __syncthreads();
    float acc = ob[c];
    #pragma unroll
    for (int kk = 0; kk < CC; kk++) acc += xs[r*CC + kk] * ows[kk*CC + c];
    #pragma unroll
    for (int kk = 0; kk < CC; kk++) acc += as_[r*CC + kk] * ows[(CC + kk)*CC + c];
    float v = xv + acc;
    yout[row*CC + c] = (v > 0.f) ? v : 0.01f * v;
}

// ---------------- host orchestration ----------------------------------------
extern "C" void kernel_launch(void* const* d_in, const int* in_sizes, int n_in,
                              void* d_out, int out_size) {
    const float* X   = (const float*)d_in[0];
    const int*   ei  = (const int*)  d_in[1];
    const float* ea  = (const float*)d_in[2];
    const float* wn1 = (const float*)d_in[3];
    const float* we1 = (const float*)d_in[4];
    const float* q1  = (const float*)d_in[5];
    const float* k1  = (const float*)d_in[6];
    const float* aw1 = (const float*)d_in[7];
    const float* ab1 = (const float*)d_in[8];
    const float* ow1 = (const float*)d_in[9];
    const float* ob1 = (const float*)d_in[10];
    const float* wn2 = (const float*)d_in[11];
    const float* we2 = (const float*)d_in[12];
    const float* q2  = (const float*)d_in[13];
    const float* k2  = (const float*)d_in[14];
    const float* aw2 = (const float*)d_in[15];
    const float* ab2 = (const float*)d_in[16];
    const float* ow2 = (const float*)d_in[17];
    const float* ob2 = (const float*)d_in[18];

    float *xp1, *xp2, *asrc1, *adst1, *asrc2, *adst2, *aggr;
    cudaGetSymbolAddress((void**)&xp1,   g_xp1);
    cudaGetSymbolAddress((void**)&xp2,   g_xp2);
    cudaGetSymbolAddress((void**)&asrc1, g_asrc1);
    cudaGetSymbolAddress((void**)&adst1, g_adst1);
    cudaGetSymbolAddress((void**)&asrc2, g_asrc2);
    cudaGetSymbolAddress((void**)&adst2, g_adst2);
    cudaGetSymbolAddress((void**)&aggr,  g_aggr);

    prep_both_kernel<<<42, 256>>>(q1, k1, aw1, ab1, we1, q2, k2, aw2, ab2, we2);
    count_kernel<<<(EE + 255)/256, 256>>>(ei);
    scan_kernel<<<1, 1024>>>();
    xform1_kernel<<<NR/8, 512>>>(X, wn1);            // launch idx 3 (ncu capture)
    scatter_kernel<<<(EE + 255)/256, 256>>>(ei);
    aggr_kernel<<<NN/8, 256>>>(xp1, asrc1, adst1, aggr, we1, ea, 0);
    mid_kernel<<<NR/8, 512>>>(ow1, ob1, wn2);
    aggr_kernel<<<NN/8, 256>>>(xp2, asrc2, adst2, aggr, we2, ea, 1);
    out2_kernel<<<NR/8, 512>>>(ow2, ob2, (float*)d_out);
}

// round 4
// speedup vs baseline: 1.1079x; 1.0049x over previous
#include <cuda_runtime.h>
#include <math_constants.h>

#define NN 10000
#define BB 4
#define EE 160000
#define CC 64
#define CE 16
#define NR (NN*BB)          // 40000 rows

// INTERLEAVED channel layout everywhere: channel c of row r lives at
// [r*64 + ilv(c)], ilv(c) = (c&31)*2 + (c>>5); unilv(p) = (p>>1) + (p&1)*32.
__device__ float g_xp1[NR*CC];
__device__ float g_xp2[NR*CC];
__device__ float g_aggr[NR*CC];
__device__ float g_asrc1[NR], g_adst1[NR];
__device__ float g_asrc2[NR], g_adst2[NR];
__device__ float g_qaw[2][CC], g_kaw[2][CC], g_wea[2][CE];
__device__ float g_abv[2];
__device__ int  g_deg[NN];
__device__ int  g_off[NN+1];
__device__ int  g_cur[NN];
__device__ int2 g_lst[EE];           // {edge id, src node}

__device__ __forceinline__ float sigmoidf(float x) {
    return 1.0f / (1.0f + __expf(-x));
}
__device__ __forceinline__ int ilv(int c)   { return (c & 31) * 2 + (c >> 5); }
__device__ __forceinline__ int unilv(int p) { return (p >> 1) + (p & 1) * 32; }

// ---------------- prep: fold attention weights (both layers) + zero deg ----
__global__ void prep_both_kernel(const float* q1, const float* k1, const float* aw1,
                                 const float* ab1, const float* we1,
                                 const float* q2, const float* k2, const float* aw2,
                                 const float* ab2, const float* we2) {
    int tid = threadIdx.x;
    if (blockIdx.x >= 2) {
        int i = (blockIdx.x - 2) * 256 + tid;
        if (i < NN) g_deg[i] = 0;
        return;
    }
    int layer = blockIdx.x;
    const float* q  = layer ? q2  : q1;
    const float* k  = layer ? k2  : k1;
    const float* aw = layer ? aw2 : aw1;
    const float* ab = layer ? ab2 : ab1;
    const float* we = layer ? we2 : we1;
    int w = tid >> 5, lane = tid & 31;
    float awq_lo = aw[lane],        awq_hi = aw[32 + lane];
    float awk_lo = aw[64 + lane],   awk_hi = aw[96 + lane];
    float aw3_lo = aw[128 + lane],  aw3_hi = aw[160 + lane];
    #pragma unroll
    for (int i = 0; i < 8; i++) {
        int row = w * 8 + i;
        float sq = q[row*CC + lane] * awq_lo + q[row*CC + 32 + lane] * awq_hi;
        float sk = k[row*CC + lane] * awk_lo + k[row*CC + 32 + lane] * awk_hi;
        #pragma unroll
        for (int o = 16; o; o >>= 1) {
            sq += __shfl_down_sync(0xffffffffu, sq, o);
            sk += __shfl_down_sync(0xffffffffu, sk, o);
        }
        if (lane == 0) { g_qaw[layer][row] = sq; g_kaw[layer][row] = sk; }
    }
    #pragma unroll
    for (int i = 0; i < 2; i++) {
        int row = w * 2 + i;
        float s = we[row*CC + lane] * aw3_lo + we[row*CC + 32 + lane] * aw3_hi;
        #pragma unroll
        for (int o = 16; o; o >>= 1) s += __shfl_down_sync(0xffffffffu, s, o);
        if (lane == 0) g_wea[layer][row] = s;
    }
    if (tid == 0) g_abv[layer] = ab[0];
}

// ---------------- CSR build -------------------------------------------------
__global__ void count_kernel(const int* __restrict__ ei) {
    int e = blockIdx.x * 256 + threadIdx.x;
    if (e < EE) atomicAdd(&g_deg[ei[EE + e]], 1);
}
__global__ void scan_kernel() {
    __shared__ int s[1024];
    const int CH = (NN + 1023) / 1024;
    int t = threadIdx.x;
    int base = t * CH;
    int local[CH];
    int sum = 0;
    #pragma unroll
    for (int i = 0; i < CH; i++) {
        local[i] = sum;
        if (base + i < NN) sum += g_deg[base + i];
    }
    s[t] = sum;
    __syncthreads();
    for (int off = 1; off < 1024; off <<= 1) {
        int v = (t >= off) ? s[t - off] : 0;
        __syncthreads();
        s[t] += v;
        __syncthreads();
    }
    int excl = (t == 0) ? 0 : s[t - 1];
    #pragma unroll
    for (int i = 0; i < CH; i++) {
        if (base + i < NN) {
            int o = excl + local[i];
            g_off[base + i] = o;
            g_cur[base + i] = o;
        }
    }
    if (t == 1023) g_off[NN] = s[1023];
}
__global__ void scatter_kernel(const int* __restrict__ ei) {
    int e = blockIdx.x * 256 + threadIdx.x;
    if (e < EE) {
        int src = ei[e];
        int dst = ei[EE + e];
        int pos = atomicAdd(&g_cur[dst], 1);
        g_lst[pos] = make_int2(e, src);
    }
}

// ---------------- layer-1 transform: register-tiled 64-row blocks ----------
// block = 256; thread tile = 4 rows x 4 interleaved-cols
__global__ void xform1_kernel(const float* __restrict__ x, const float* __restrict__ wn) {
    __shared__ float ws[CC*CC];     // weight, rows natural k, cols interleaved
    __shared__ float xs[64*CC];     // input rows, natural channels
    __shared__ float qs[CC], ks_[CC];
    __shared__ float redq[64], redk[64];
    int tid = threadIdx.x;
    for (int i = tid; i < CC*CC; i += 256) {
        int kk = i >> 6, c = i & 63;
        ws[kk*CC + ilv(c)] = wn[i];
    }
    if (tid < CC) { qs[tid] = g_qaw[0][unilv(tid)]; ks_[tid] = g_kaw[0][unilv(tid)]; }
    int row0 = blockIdx.x * 64;
    for (int i = tid*4; i < 64*CC; i += 1024)
        *(float4*)&xs[i] = *(const float4*)&x[row0*CC + i];
    __syncthreads();
    int tc = tid & 15, tg = tid >> 4;
    int r0 = tg * 4;
    float acc[4][4] = {};
    #pragma unroll 16
    for (int kk = 0; kk < CC; kk++) {
        float4 w = *(float4*)&ws[kk*CC + tc*4];
        float a0 = xs[(r0+0)*CC+kk], a1 = xs[(r0+1)*CC+kk];
        float a2 = xs[(r0+2)*CC+kk], a3 = xs[(r0+3)*CC+kk];
        acc[0][0]+=a0*w.x; acc[0][1]+=a0*w.y; acc[0][2]+=a0*w.z; acc[0][3]+=a0*w.w;
        acc[1][0]+=a1*w.x; acc[1][1]+=a1*w.y; acc[1][2]+=a1*w.z; acc[1][3]+=a1*w.w;
        acc[2][0]+=a2*w.x; acc[2][1]+=a2*w.y; acc[2][2]+=a2*w.z; acc[2][3]+=a2*w.w;
        acc[3][0]+=a3*w.x; acc[3][1]+=a3*w.y; acc[3][2]+=a3*w.z; acc[3][3]+=a3*w.w;
    }
    float4 qv = *(float4*)&qs[tc*4];
    float4 kv = *(float4*)&ks_[tc*4];
    #pragma unroll
    for (int i = 0; i < 4; i++) {
        int row = row0 + r0 + i;
        *(float4*)&g_xp1[row*CC + tc*4] = make_float4(acc[i][0], acc[i][1], acc[i][2], acc[i][3]);
        float pq = acc[i][0]*qv.x + acc[i][1]*qv.y + acc[i][2]*qv.z + acc[i][3]*qv.w;
        float pk = acc[i][0]*kv.x + acc[i][1]*kv.y + acc[i][2]*kv.z + acc[i][3]*kv.w;
        #pragma unroll
        for (int o = 8; o; o >>= 1) {
            pq += __shfl_down_sync(0xffffffffu, pq, o, 16);
            pk += __shfl_down_sync(0xffffffffu, pk, o, 16);
        }
        if (tc == 0) { redq[tg*4 + i] = pq; redk[tg*4 + i] = pk; }
    }
    __syncthreads();
    if (tid < 64) {
        g_asrc1[row0 + tid] = redq[tid];
        g_adst1[row0 + tid] = redk[tid];
    }
}

// ---------------- segment max with INLINE gate: one warp per node ----------
__global__ void aggr_kernel(const float* __restrict__ xp, const float* __restrict__ asrcp,
                            const float* __restrict__ adstp, float* __restrict__ aggrp,
                            const float* __restrict__ we, const float* __restrict__ eattr,
                            int layer) {
    __shared__ float wes[CE*CC];
    __shared__ float weas[CE];
    int tid = threadIdx.x;
    for (int i = tid; i < CE*CC; i += 256) wes[i] = we[i];
    if (tid < CE) weas[tid] = g_wea[layer][tid];
    __syncthreads();
    float abv = g_abv[layer];
    int n = blockIdx.x * 8 + (tid >> 5);
    int lane = tid & 31;
    int beg = g_off[n], end = g_off[n+1];
    float4 ad = *(const float4*)&adstp[n*4];
    float mx0[BB], mx1[BB];
    #pragma unroll
    for (int b = 0; b < BB; b++) { mx0[b] = -CUDART_INF_F; mx1[b] = -CUDART_INF_F; }
    for (int i = beg; i < end; i++) {
        int2 es = g_lst[i];
        int e = es.x, src = es.y;
        float av = eattr[e*CE + (lane & 15)];
        float acc1 = 0.f, acc2 = 0.f;
        #pragma unroll
        for (int j = 0; j < CE; j++) {
            float aj = __shfl_sync(0xffffffffu, av, j);
            acc1 += aj * wes[j*CC + lane];
            acc2 += aj * wes[j*CC + 32 + lane];
        }
        float gA = sigmoidf(acc1);
        float gB = sigmoidf(acc2);
        float sc = av * weas[lane & 15];
        sc += __shfl_xor_sync(0xffffffffu, sc, 8);
        sc += __shfl_xor_sync(0xffffffffu, sc, 4);
        sc += __shfl_xor_sync(0xffffffffu, sc, 2);
        sc += __shfl_xor_sync(0xffffffffu, sc, 1);
        float esc = sc + abv;
        float4 as = *(const float4*)&asrcp[src*4];
        float attv[BB];
        attv[0] = sigmoidf(as.x + ad.x + esc);
        attv[1] = sigmoidf(as.y + ad.y + esc);
        attv[2] = sigmoidf(as.z + ad.z + esc);
        attv[3] = sigmoidf(as.w + ad.w + esc);
        #pragma unroll
        for (int b = 0; b < BB; b++) {
            float2 x = *(const float2*)&xp[(src*BB + b)*CC + lane*2];
            mx0[b] = fmaxf(mx0[b], attv[b] * x.x * gA);
            mx1[b] = fmaxf(mx1[b], attv[b] * x.y * gB);
        }
    }
    bool empty = (beg == end);
    #pragma unroll
    for (int b = 0; b < BB; b++) {
        float2 o = empty ? make_float2(0.f, 0.f) : make_float2(mx0[b], mx1[b]);
        *(float2*)&aggrp[(n*BB + b)*CC + lane*2] = o;
    }
}

// ---------------- fused: layer1 output + layer2 transform ------------------
// dynamic smem: ows(8192) + wns(4096) + xs(4096) + as(4096) + ys(4096) floats
__global__ void mid_kernel(const float* __restrict__ ow, const float* __restrict__ ob,
                           const float* __restrict__ wn2) {
    extern __shared__ float sm[];
    float* ows = sm;                 // [128][64] k natural-split, cols interleaved, k interleaved within halves
    float* wns = ows + 2*CC*CC;      // [64][64] both interleaved
    float* xs  = wns + CC*CC;        // xp1, interleaved
    float* as_ = xs + 64*CC;         // aggr, interleaved
    float* ys  = as_ + 64*CC;        // y1, interleaved
    __shared__ float obi[CC], qs[CC], ks_[CC];
    __shared__ float redq[64], redk[64];
    int tid = threadIdx.x;
    for (int i = tid; i < 2*CC*CC; i += 256) {
        int k = i >> 6, c = i & 63;
        int pk = (k < CC) ? ilv(k) : CC + ilv(k - CC);
        ows[pk*CC + ilv(c)] = ow[i];
    }
    for (int i = tid; i < CC*CC; i += 256) {
        int k = i >> 6, c = i & 63;
        wns[ilv(k)*CC + ilv(c)] = wn2[i];
    }
    if (tid < CC) {
        int c = unilv(tid);
        obi[tid] = ob[c];
        qs[tid]  = g_qaw[1][c];
        ks_[tid] = g_kaw[1][c];
    }
    int row0 = blockIdx.x * 64;
    for (int i = tid*4; i < 64*CC; i += 1024) {
        *(float4*)&xs[i]  = *(const float4*)&g_xp1[row0*CC + i];
        *(float4*)&as_[i] = *(const float4*)&g_aggr[row0*CC + i];
    }
    __syncthreads();
    int tc = tid & 15, tg = tid >> 4;
    int r0 = tg * 4;
    float acc[4][4];
    {
        float4 bv = *(float4*)&obi[tc*4];
        #pragma unroll
        for (int i = 0; i < 4; i++) { acc[i][0]=bv.x; acc[i][1]=bv.y; acc[i][2]=bv.z; acc[i][3]=bv.w; }
    }
    #pragma unroll 16
    for (int kk = 0; kk < CC; kk++) {
        float4 w = *(float4*)&ows[kk*CC + tc*4];
        float a0 = xs[(r0+0)*CC+kk], a1 = xs[(r0+1)*CC+kk];
        float a2 = xs[(r0+2)*CC+kk], a3 = xs[(r0+3)*CC+kk];
        acc[0][0]+=a0*w.x; acc[0][1]+=a0*w.y; acc[0][2]+=a0*w.z; acc[0][3]+=a0*w.w;
        acc[1][0]+=a1*w.x; acc[1][1]+=a1*w.y; acc[1][2]+=a1*w.z; acc[1][3]+=a1*w.w;
        acc[2][0]+=a2*w.x; acc[2][1]+=a2*w.y; acc[2][2]+=a2*w.z; acc[2][3]+=a2*w.w;
        acc[3][0]+=a3*w.x; acc[3][1]+=a3*w.y; acc[3][2]+=a3*w.z; acc[3][3]+=a3*w.w;
    }
    #pragma unroll 16
    for (int kk = 0; kk < CC; kk++) {
        float4 w = *(float4*)&ows[(CC+kk)*CC + tc*4];
        float a0 = as_[(r0+0)*CC+kk], a1 = as_[(r0+1)*CC+kk];
        float a2 = as_[(r0+2)*CC+kk], a3 = as_[(r0+3)*CC+kk];
        acc[0][0]+=a0*w.x; acc[0][1]+=a0*w.y; acc[0][2]+=a0*w.z; acc[0][3]+=a0*w.w;
        acc[1][0]+=a1*w.x; acc[1][1]+=a1*w.y; acc[1][2]+=a1*w.z; acc[1][3]+=a1*w.w;
        acc[2][0]+=a2*w.x; acc[2][1]+=a2*w.y; acc[2][2]+=a2*w.z; acc[2][3]+=a2*w.w;
        acc[3][0]+=a3*w.x; acc[3][1]+=a3*w.y; acc[3][2]+=a3*w.z; acc[3][3]+=a3*w.w;
    }
    #pragma unroll
    for (int i = 0; i < 4; i++) {
        #pragma unroll
        for (int j = 0; j < 4; j++) {
            float v = xs[(r0+i)*CC + tc*4 + j] + acc[i][j];
            ys[(r0+i)*CC + tc*4 + j] = (v > 0.f) ? v : 0.01f * v;
        }
    }
    __syncthreads();
    float acc2[4][4] = {};
    #pragma unroll 16
    for (int kk = 0; kk < CC; kk++) {
        float4 w = *(float4*)&wns[kk*CC + tc*4];
        float a0 = ys[(r0+0)*CC+kk], a1 = ys[(r0+1)*CC+kk];
        float a2 = ys[(r0+2)*CC+kk], a3 = ys[(r0+3)*CC+kk];
        acc2[0][0]+=a0*w.x; acc2[0][1]+=a0*w.y; acc2[0][2]+=a0*w.z; acc2[0][3]+=a0*w.w;
        acc2[1][0]+=a1*w.x; acc2[1][1]+=a1*w.y; acc2[1][2]+=a1*w.z; acc2[1][3]+=a1*w.w;
        acc2[2][0]+=a2*w.x; acc2[2][1]+=a2*w.y; acc2[2][2]+=a2*w.z; acc2[2][3]+=a2*w.w;
        acc2[3][0]+=a3*w.x; acc2[3][1]+=a3*w.y; acc2[3][2]+=a3*w.z; acc2[3][3]+=a3*w.w;
    }
    float4 qv = *(float4*)&qs[tc*4];
    float4 kv = *(float4*)&ks_[tc*4];
    #pragma unroll
    for (int i = 0; i < 4; i++) {
        int row = row0 + r0 + i;
        *(float4*)&g_xp2[row*CC + tc*4] = make_float4(acc2[i][0], acc2[i][1], acc2[i][2], acc2[i][3]);
        float pq = acc2[i][0]*qv.x + acc2[i][1]*qv.y + acc2[i][2]*qv.z + acc2[i][3]*qv.w;
        float pk = acc2[i][0]*kv.x + acc2[i][1]*kv.y + acc2[i][2]*kv.z + acc2[i][3]*kv.w;
        #pragma unroll
        for (int o = 8; o; o >>= 1) {
            pq += __shfl_down_sync(0xffffffffu, pq, o, 16);
            pk += __shfl_down_sync(0xffffffffu, pk, o, 16);
        }
        if (tc == 0) { redq[tg*4 + i] = pq; redk[tg*4 + i] = pk; }
    }
    __syncthreads();
    if (tid < 64) {
        g_asrc2[row0 + tid] = redq[tid];
        g_adst2[row0 + tid] = redk[tid];
    }
}

// ---------------- final output ----------------------------------------------
// dynamic smem: ows(8192) + xs(4096) + as(4096) floats = 64KB
__global__ void out2_kernel(const float* __restrict__ ow, const float* __restrict__ ob,
                            float* __restrict__ yout) {
    extern __shared__ float sm[];
    float* ows = sm;
    float* xs  = ows + 2*CC*CC;
    float* as_ = xs + 64*CC;
    __shared__ float obi[CC];
    int tid = threadIdx.x;
    for (int i = tid; i < 2*CC*CC; i += 256) {
        int k = i >> 6, c = i & 63;
        int pk = (k < CC) ? ilv(k) : CC + ilv(k - CC);
        ows[pk*CC + ilv(c)] = ow[i];
    }
    if (tid < CC) obi[tid] = ob[unilv(tid)];
    int row0 = blockIdx.x * 64;
    for (int i = tid*4; i < 64*CC; i += 1024) {
        *(float4*)&xs[i]  = *(const float4*)&g_xp2[row0*CC + i];
        *(float4*)&as_[i] = *(const float4*)&g_aggr[row0*CC + i];
    }
    __syncthreads();
    int tc = tid & 15, tg = tid >> 4;
    int r0 = tg * 4;
    float acc[4][4];
    {
        float4 bv = *(float4*)&obi[tc*4];
        #pragma unroll
        for (int i = 0; i < 4; i++) { acc[i][0]=bv.x; acc[i][1]=bv.y; acc[i][2]=bv.z; acc[i][3]=bv.w; }
    }
    #pragma unroll 16
    for (int kk = 0; kk < CC; kk++) {
        float4 w = *(float4*)&ows[kk*CC + tc*4];
        float a0 = xs[(r0+0)*CC+kk], a1 = xs[(r0+1)*CC+kk];
        float a2 = xs[(r0+2)*CC+kk], a3 = xs[(r0+3)*CC+kk];
        acc[0][0]+=a0*w.x; acc[0][1]+=a0*w.y; acc[0][2]+=a0*w.z; acc[0][3]+=a0*w.w;
        acc[1][0]+=a1*w.x; acc[1][1]+=a1*w.y; acc[1][2]+=a1*w.z; acc[1][3]+=a1*w.w;
        acc[2][0]+=a2*w.x; acc[2][1]+=a2*w.y; acc[2][2]+=a2*w.z; acc[2][3]+=a2*w.w;
        acc[3][0]+=a3*w.x; acc[3][1]+=a3*w.y; acc[3][2]+=a3*w.z; acc[3][3]+=a3*w.w;
    }
    #pragma unroll 16
    for (int kk = 0; kk < CC; kk++) {
        float4 w = *(float4*)&ows[(CC+kk)*CC + tc*4];
        float a0 = as_[(r0+0)*CC+kk], a1 = as_[(r0+1)*CC+kk];
        float a2 = as_[(r0+2)*CC+kk], a3 = as_[(r0+3)*CC+kk];
        acc[0][0]+=a0*w.x; acc[0][1]+=a0*w.y; acc[0][2]+=a0*w.z; acc[0][3]+=a0*w.w;
        acc[1][0]+=a1*w.x; acc[1][1]+=a1*w.y; acc[1][2]+=a1*w.z; acc[1][3]+=a1*w.w;
        acc[2][0]+=a2*w.x; acc[2][1]+=a2*w.y; acc[2][2]+=a2*w.z; acc[2][3]+=a2*w.w;
        acc[3][0]+=a3*w.x; acc[3][1]+=a3*w.y; acc[3][2]+=a3*w.z; acc[3][3]+=a3*w.w;
    }
    #pragma unroll
    for (int i = 0; i < 4; i++) {
        int row = row0 + r0 + i;
        #pragma unroll
        for (int j = 0; j < 4; j++) {
            int p = tc*4 + j;
            float v = xs[(r0+i)*CC + p] + acc[i][j];
            yout[row*CC + unilv(p)] = (v > 0.f) ? v : 0.01f * v;
        }
    }
}

// ---------------- host orchestration ----------------------------------------
extern "C" void kernel_launch(void* const* d_in, const int* in_sizes, int n_in,
                              void* d_out, int out_size) {
    const float* X   = (const float*)d_in[0];
    const int*   ei  = (const int*)  d_in[1];
    const float* ea  = (const float*)d_in[2];
    const float* wn1 = (const float*)d_in[3];
    const float* we1 = (const float*)d_in[4];
    const float* q1  = (const float*)d_in[5];
    const float* k1  = (const float*)d_in[6];
    const float* aw1 = (const float*)d_in[7];
    const float* ab1 = (const float*)d_in[8];
    const float* ow1 = (const float*)d_in[9];
    const float* ob1 = (const float*)d_in[10];
    const float* wn2 = (const float*)d_in[11];
    const float* we2 = (const float*)d_in[12];
    const float* q2  = (const float*)d_in[13];
    const float* k2  = (const float*)d_in[14];
    const float* aw2 = (const float*)d_in[15];
    const float* ab2 = (const float*)d_in[16];
    const float* ow2 = (const float*)d_in[17];
    const float* ob2 = (const float*)d_in[18];

    float *xp1, *xp2, *asrc1, *adst1, *asrc2, *adst2, *aggr;
    cudaGetSymbolAddress((void**)&xp1,   g_xp1);
    cudaGetSymbolAddress((void**)&xp2,   g_xp2);
    cudaGetSymbolAddress((void**)&asrc1, g_asrc1);
    cudaGetSymbolAddress((void**)&adst1, g_adst1);
    cudaGetSymbolAddress((void**)&asrc2, g_asrc2);
    cudaGetSymbolAddress((void**)&adst2, g_adst2);
    cudaGetSymbolAddress((void**)&aggr,  g_aggr);

    const int MID_SMEM = (2*CC*CC + CC*CC + 3*64*CC) * 4;   // 96 KB
    const int OUT_SMEM = (2*CC*CC + 2*64*CC) * 4;           // 64 KB
    static bool attr_done = false;
    if (!attr_done) {
        cudaFuncSetAttribute(mid_kernel,  cudaFuncAttributeMaxDynamicSharedMemorySize, MID_SMEM);
        cudaFuncSetAttribute(out2_kernel, cudaFuncAttributeMaxDynamicSharedMemorySize, OUT_SMEM);
        attr_done = true;
    }

    prep_both_kernel<<<42, 256>>>(q1, k1, aw1, ab1, we1, q2, k2, aw2, ab2, we2);
    count_kernel<<<(EE + 255)/256, 256>>>(ei);
    scan_kernel<<<1, 1024>>>();
    xform1_kernel<<<NR/64, 256>>>(X, wn1);            // launch idx 3 (ncu capture)
    scatter_kernel<<<(EE + 255)/256, 256>>>(ei);
    aggr_kernel<<<NN/8, 256>>>(xp1, asrc1, adst1, aggr, we1, ea, 0);
    mid_kernel<<<NR/64, 256, MID_SMEM>>>(ow1, ob1, wn2);
    aggr_kernel<<<NN/8, 256>>>(xp2, asrc2, adst2, aggr, we2, ea, 1);
    out2_kernel<<<NR/64, 256, OUT_SMEM>>>(ow2, ob2, (float*)d_out);
}

// round 5
// speedup vs baseline: 1.3045x; 1.1775x over previous
#include <cuda_runtime.h>
#include <math_constants.h>

#define NN 10000
#define BB 4
#define EE 160000
#define CC 64
#define CE 16
#define NR (NN*BB)          // 40000 rows
#define XSTRIDE 68          // padded row stride for transposed activation tiles

// INTERLEAVED channel layout for node tensors: channel c of row r lives at
// [r*64 + ilv(c)], ilv(c) = (c&31)*2 + (c>>5); unilv(p) = (p>>1) + (p&1)*32.
__device__ float  g_xp1[NR*CC];
__device__ float  g_xp2[NR*CC];
__device__ float  g_aggr[NR*CC];
__device__ float  g_asrc1[NR], g_adst1[NR];
__device__ float  g_asrc2[NR], g_adst2[NR];
__device__ float  g_qaw[2][CC], g_kaw[2][CC], g_wea[2][CE];
__device__ float  g_abv[2];
__device__ float2 g_esc[EE];         // per-edge attention scalar, both layers
__device__ int  g_deg[NN];
__device__ int  g_off[NN+1];
__device__ int  g_cur[NN];
__device__ int2 g_lst[EE];           // {edge id, src node}

__device__ __forceinline__ float sigmoidf(float x) {
    return 1.0f / (1.0f + __expf(-x));
}
__device__ __forceinline__ int ilv(int c)   { return (c & 31) * 2 + (c >> 5); }
__device__ __forceinline__ int unilv(int p) { return (p >> 1) + (p & 1) * 32; }

// ---------------- prep: fold attention weights (both layers) + zero deg ----
__global__ void prep_both_kernel(const float* q1, const float* k1, const float* aw1,
                                 const float* ab1, const float* we1,
                                 const float* q2, const float* k2, const float* aw2,
                                 const float* ab2, const float* we2) {
    int tid = threadIdx.x;
    if (blockIdx.x >= 2) {
        int i = (blockIdx.x - 2) * 256 + tid;
        if (i < NN) g_deg[i] = 0;
        return;
    }
    int layer = blockIdx.x;
    const float* q  = layer ? q2  : q1;
    const float* k  = layer ? k2  : k1;
    const float* aw = layer ? aw2 : aw1;
    const float* ab = layer ? ab2 : ab1;
    const float* we = layer ? we2 : we1;
    int w = tid >> 5, lane = tid & 31;
    float awq_lo = aw[lane],        awq_hi = aw[32 + lane];
    float awk_lo = aw[64 + lane],   awk_hi = aw[96 + lane];
    float aw3_lo = aw[128 + lane],  aw3_hi = aw[160 + lane];
    #pragma unroll
    for (int i = 0; i < 8; i++) {
        int row = w * 8 + i;
        float sq = q[row*CC + lane] * awq_lo + q[row*CC + 32 + lane] * awq_hi;
        float sk = k[row*CC + lane] * awk_lo + k[row*CC + 32 + lane] * awk_hi;
        #pragma unroll
        for (int o = 16; o; o >>= 1) {
            sq += __shfl_down_sync(0xffffffffu, sq, o);
            sk += __shfl_down_sync(0xffffffffu, sk, o);
        }
        if (lane == 0) { g_qaw[layer][row] = sq; g_kaw[layer][row] = sk; }
    }
    #pragma unroll
    for (int i = 0; i < 2; i++) {
        int row = w * 2 + i;
        float s = we[row*CC + lane] * aw3_lo + we[row*CC + 32 + lane] * aw3_hi;
        #pragma unroll
        for (int o = 16; o; o >>= 1) s += __shfl_down_sync(0xffffffffu, s, o);
        if (lane == 0) g_wea[layer][row] = s;
    }
    if (tid == 0) g_abv[layer] = ab[0];
}

// ---------------- CSR build -------------------------------------------------
__global__ void count_kernel(const int* __restrict__ ei) {
    int e = blockIdx.x * 256 + threadIdx.x;
    if (e < EE) atomicAdd(&g_deg[ei[EE + e]], 1);
}
__global__ void scan_kernel() {
    __shared__ int s[1024];
    const int CH = (NN + 1023) / 1024;
    int t = threadIdx.x;
    int base = t * CH;
    int local[CH];
    int sum = 0;
    #pragma unroll
    for (int i = 0; i < CH; i++) {
        local[i] = sum;
        if (base + i < NN) sum += g_deg[base + i];
    }
    s[t] = sum;
    __syncthreads();
    for (int off = 1; off < 1024; off <<= 1) {
        int v = (t >= off) ? s[t - off] : 0;
        __syncthreads();
        s[t] += v;
        __syncthreads();
    }
    int excl = (t == 0) ? 0 : s[t - 1];
    #pragma unroll
    for (int i = 0; i < CH; i++) {
        if (base + i < NN) {
            int o = excl + local[i];
            g_off[base + i] = o;
            g_cur[base + i] = o;
        }
    }
    if (t == 1023) g_off[NN] = s[1023];
}
__global__ void scatter_kernel(const int* __restrict__ ei) {
    int e = blockIdx.x * 256 + threadIdx.x;
    if (e < EE) {
        int src = ei[e];
        int dst = ei[EE + e];
        int pos = atomicAdd(&g_cur[dst], 1);
        g_lst[pos] = make_int2(e, src);
    }
}

// ---------------- per-edge attention scalar, both layers -------------------
__global__ void escal_kernel(const float* __restrict__ eattr) {
    __shared__ float w1[CE], w2[CE];
    __shared__ float ab0, ab1;
    int tid = threadIdx.x;
    if (tid < CE) { w1[tid] = g_wea[0][tid]; w2[tid] = g_wea[1][tid]; }
    if (tid == 0) { ab0 = g_abv[0]; ab1 = g_abv[1]; }
    __syncthreads();
    int e = blockIdx.x * 256 + tid;
    const float4* p = (const float4*)(eattr + (size_t)e * CE);
    float4 A = p[0], B = p[1], C = p[2], D = p[3];
    float a[16] = {A.x,A.y,A.z,A.w, B.x,B.y,B.z,B.w, C.x,C.y,C.z,C.w, D.x,D.y,D.z,D.w};
    float s1 = 0.f, s2 = 0.f;
    #pragma unroll
    for (int j = 0; j < CE; j++) { s1 += a[j]*w1[j]; s2 += a[j]*w2[j]; }
    g_esc[e] = make_float2(s1 + ab0, s2 + ab1);
}

// ---------------- layer-1 transform: transposed-x register-tiled GEMM ------
// block = 256; thread tile = 4 rows x 4 interleaved-cols; 64 rows per block
__global__ void xform1_kernel(const float* __restrict__ x, const float* __restrict__ wn) {
    __shared__ __align__(16) float ws[CC*CC];         // [k][interleaved c]
    __shared__ __align__(16) float xs_t[CC*XSTRIDE];  // [k][row]
    __shared__ float qs[CC], ks_[CC];
    __shared__ float redq[64], redk[64];
    int tid = threadIdx.x;
    for (int i = tid; i < CC*CC; i += 256) {
        int kk = i >> 6, c = i & 63;
        ws[kk*CC + ilv(c)] = wn[i];
    }
    if (tid < CC) { qs[tid] = g_qaw[0][unilv(tid)]; ks_[tid] = g_kaw[0][unilv(tid)]; }
    int row0 = blockIdx.x * 64;
    for (int i = tid*4; i < 64*CC; i += 1024) {
        float4 v = *(const float4*)&x[row0*CC + i];
        int r = i >> 6, c0 = i & 63;
        xs_t[(c0+0)*XSTRIDE + r] = v.x;
        xs_t[(c0+1)*XSTRIDE + r] = v.y;
        xs_t[(c0+2)*XSTRIDE + r] = v.z;
        xs_t[(c0+3)*XSTRIDE + r] = v.w;
    }
    __syncthreads();
    int tc = tid & 15, tg = tid >> 4;
    int r0 = tg * 4;
    float acc[4][4] = {};
    #pragma unroll 16
    for (int kk = 0; kk < CC; kk++) {
        float4 w = *(float4*)&ws[kk*CC + tc*4];
        float4 a = *(float4*)&xs_t[kk*XSTRIDE + r0];
        acc[0][0]+=a.x*w.x; acc[0][1]+=a.x*w.y; acc[0][2]+=a.x*w.z; acc[0][3]+=a.x*w.w;
        acc[1][0]+=a.y*w.x; acc[1][1]+=a.y*w.y; acc[1][2]+=a.y*w.z; acc[1][3]+=a.y*w.w;
        acc[2][0]+=a.z*w.x; acc[2][1]+=a.z*w.y; acc[2][2]+=a.z*w.z; acc[2][3]+=a.z*w.w;
        acc[3][0]+=a.w*w.x; acc[3][1]+=a.w*w.y; acc[3][2]+=a.w*w.z; acc[3][3]+=a.w*w.w;
    }
    float4 qv = *(float4*)&qs[tc*4];
    float4 kv = *(float4*)&ks_[tc*4];
    #pragma unroll
    for (int i = 0; i < 4; i++) {
        int row = row0 + r0 + i;
        *(float4*)&g_xp1[row*CC + tc*4] = make_float4(acc[i][0], acc[i][1], acc[i][2], acc[i][3]);
        float pq = acc[i][0]*qv.x + acc[i][1]*qv.y + acc[i][2]*qv.z + acc[i][3]*qv.w;
        float pk = acc[i][0]*kv.x + acc[i][1]*kv.y + acc[i][2]*kv.z + acc[i][3]*kv.w;
        #pragma unroll
        for (int o = 8; o; o >>= 1) {
            pq += __shfl_down_sync(0xffffffffu, pq, o, 16);
            pk += __shfl_down_sync(0xffffffffu, pk, o, 16);
        }
        if (tc == 0) { redq[tg*4 + i] = pq; redk[tg*4 + i] = pk; }
    }
    __syncthreads();
    if (tid < 64) {
        g_asrc1[row0 + tid] = redq[tid];
        g_adst1[row0 + tid] = redk[tid];
    }
}

// ---------------- segment max, no shfl, precomputed escal ------------------
// one warp per node, block = 256 (8 nodes)
__global__ void aggr_kernel(const float* __restrict__ xp, const float* __restrict__ asrcp,
                            const float* __restrict__ adstp, float* __restrict__ aggrp,
                            const float* __restrict__ we, const float* __restrict__ eattr,
                            int layer) {
    __shared__ float wes2[CE*CC];    // [j][interleaved c] -> float2 per lane
    int tid = threadIdx.x;
    for (int i = tid; i < CE*CC; i += 256) {
        int j = i >> 6, c = i & 63;
        wes2[j*CC + ilv(c)] = we[i];
    }
    __syncthreads();
    int n = blockIdx.x * 8 + (tid >> 5);
    int lane = tid & 31;
    int beg = g_off[n], end = g_off[n+1];
    float4 ad = *(const float4*)&adstp[n*4];
    float mx0[BB], mx1[BB];
    #pragma unroll
    for (int b = 0; b < BB; b++) { mx0[b] = -CUDART_INF_F; mx1[b] = -CUDART_INF_F; }
    const float* W = wes2 + lane*2;
    int2 nx = (beg < end) ? g_lst[beg] : make_int2(0, 0);
    for (int i = beg; i < end; i++) {
        int e = nx.x, src = nx.y;
        if (i + 1 < end) nx = g_lst[i+1];
        // uniform broadcast loads of edge_attr (no shfl)
        const float4* p4 = (const float4*)(eattr + (size_t)e * CE);
        float4 A = p4[0], B = p4[1], Cv = p4[2], D = p4[3];
        float2 e2 = g_esc[e];
        float esc = layer ? e2.y : e2.x;
        float4 as = *(const float4*)&asrcp[src*4];
        // gate dot: two interleaved chains of float2 FMAs
        float2 acc0 = make_float2(0.f, 0.f), acc1 = make_float2(0.f, 0.f);
        float av[16] = {A.x,A.y,A.z,A.w, B.x,B.y,B.z,B.w, Cv.x,Cv.y,Cv.z,Cv.w, D.x,D.y,D.z,D.w};
        #pragma unroll
        for (int j = 0; j < CE; j += 2) {
            float2 w0 = *(const float2*)&W[(j  )*CC];
            float2 w1 = *(const float2*)&W[(j+1)*CC];
            acc0.x += av[j]*w0.x;   acc0.y += av[j]*w0.y;
            acc1.x += av[j+1]*w1.x; acc1.y += av[j+1]*w1.y;
        }
        float gA = sigmoidf(acc0.x + acc1.x);
        float gB = sigmoidf(acc0.y + acc1.y);
        float attv[BB];
        attv[0] = sigmoidf(as.x + ad.x + esc);
        attv[1] = sigmoidf(as.y + ad.y + esc);
        attv[2] = sigmoidf(as.z + ad.z + esc);
        attv[3] = sigmoidf(as.w + ad.w + esc);
        #pragma unroll
        for (int b = 0; b < BB; b++) {
            float2 x = *(const float2*)&xp[(src*BB + b)*CC + lane*2];
            mx0[b] = fmaxf(mx0[b], attv[b] * x.x * gA);
            mx1[b] = fmaxf(mx1[b], attv[b] * x.y * gB);
        }
    }
    bool empty = (beg == end);
    #pragma unroll
    for (int b = 0; b < BB; b++) {
        float2 o = empty ? make_float2(0.f, 0.f) : make_float2(mx0[b], mx1[b]);
        *(float2*)&aggrp[(n*BB + b)*CC + lane*2] = o;
    }
}

// ---------------- fused: layer1 output + layer2 transform ------------------
__global__ void mid_kernel(const float* __restrict__ ow, const float* __restrict__ ob,
                           const float* __restrict__ wn2) {
    extern __shared__ __align__(16) float sm[];
    float* ows  = sm;                        // 8192
    float* wns  = ows + 2*CC*CC;             // 4096
    float* xs_t = wns + CC*CC;               // CC*XSTRIDE
    float* as_t = xs_t + CC*XSTRIDE;
    float* ys_t = as_t + CC*XSTRIDE;
    __shared__ float obi[CC], qs[CC], ks_[CC];
    __shared__ float redq[64], redk[64];
    int tid = threadIdx.x;
    for (int i = tid; i < 2*CC*CC; i += 256) {
        int k = i >> 6, c = i & 63;
        int pk = (k < CC) ? ilv(k) : CC + ilv(k - CC);
        ows[pk*CC + ilv(c)] = ow[i];
    }
    for (int i = tid; i < CC*CC; i += 256) {
        int k = i >> 6, c = i & 63;
        wns[ilv(k)*CC + ilv(c)] = wn2[i];
    }
    if (tid < CC) {
        int c = unilv(tid);
        obi[tid] = ob[c];
        qs[tid]  = g_qaw[1][c];
        ks_[tid] = g_kaw[1][c];
    }
    int row0 = blockIdx.x * 64;
    for (int i = tid*4; i < 64*CC; i += 1024) {
        int r = i >> 6, p0 = i & 63;
        float4 v = *(const float4*)&g_xp1[row0*CC + i];
        xs_t[(p0+0)*XSTRIDE + r] = v.x;
        xs_t[(p0+1)*XSTRIDE + r] = v.y;
        xs_t[(p0+2)*XSTRIDE + r] = v.z;
        xs_t[(p0+3)*XSTRIDE + r] = v.w;
        float4 u = *(const float4*)&g_aggr[row0*CC + i];
        as_t[(p0+0)*XSTRIDE + r] = u.x;
        as_t[(p0+1)*XSTRIDE + r] = u.y;
        as_t[(p0+2)*XSTRIDE + r] = u.z;
        as_t[(p0+3)*XSTRIDE + r] = u.w;
    }
    __syncthreads();
    int tc = tid & 15, tg = tid >> 4;
    int r0 = tg * 4;
    float acc[4][4];
    {
        float4 bv = *(float4*)&obi[tc*4];
        #pragma unroll
        for (int i = 0; i < 4; i++) { acc[i][0]=bv.x; acc[i][1]=bv.y; acc[i][2]=bv.z; acc[i][3]=bv.w; }
    }
    #pragma unroll 16
    for (int kk = 0; kk < CC; kk++) {
        float4 w = *(float4*)&ows[kk*CC + tc*4];
        float4 a = *(float4*)&xs_t[kk*XSTRIDE + r0];
        acc[0][0]+=a.x*w.x; acc[0][1]+=a.x*w.y; acc[0][2]+=a.x*w.z; acc[0][3]+=a.x*w.w;
        acc[1][0]+=a.y*w.x; acc[1][1]+=a.y*w.y; acc[1][2]+=a.y*w.z; acc[1][3]+=a.y*w.w;
        acc[2][0]+=a.z*w.x; acc[2][1]+=a.z*w.y; acc[2][2]+=a.z*w.z; acc[2][3]+=a.z*w.w;
        acc[3][0]+=a.w*w.x; acc[3][1]+=a.w*w.y; acc[3][2]+=a.w*w.z; acc[3][3]+=a.w*w.w;
    }
    #pragma unroll 16
    for (int kk = 0; kk < CC; kk++) {
        float4 w = *(float4*)&ows[(CC+kk)*CC + tc*4];
        float4 a = *(float4*)&as_t[kk*XSTRIDE + r0];
        acc[0][0]+=a.x*w.x; acc[0][1]+=a.x*w.y; acc[0][2]+=a.x*w.z; acc[0][3]+=a.x*w.w;
        acc[1][0]+=a.y*w.x; acc[1][1]+=a.y*w.y; acc[1][2]+=a.y*w.z; acc[1][3]+=a.y*w.w;
        acc[2][0]+=a.z*w.x; acc[2][1]+=a.z*w.y; acc[2][2]+=a.z*w.z; acc[2][3]+=a.z*w.w;
        acc[3][0]+=a.w*w.x; acc[3][1]+=a.w*w.y; acc[3][2]+=a.w*w.z; acc[3][3]+=a.w*w.w;
    }
    #pragma unroll
    for (int i = 0; i < 4; i++) {
        #pragma unroll
        for (int j = 0; j < 4; j++) {
            int p = tc*4 + j, r = r0 + i;
            float v = xs_t[p*XSTRIDE + r] + acc[i][j];
            ys_t[p*XSTRIDE + r] = (v > 0.f) ? v : 0.01f * v;
        }
    }
    __syncthreads();
    float acc2[4][4] = {};
    #pragma unroll 16
    for (int kk = 0; kk < CC; kk++) {
        float4 w = *(float4*)&wns[kk*CC + tc*4];
        float4 a = *(float4*)&ys_t[kk*XSTRIDE + r0];
        acc2[0][0]+=a.x*w.x; acc2[0][1]+=a.x*w.y; acc2[0][2]+=a.x*w.z; acc2[0][3]+=a.x*w.w;
        acc2[1][0]+=a.y*w.x; acc2[1][1]+=a.y*w.y; acc2[1][2]+=a.y*w.z; acc2[1][3]+=a.y*w.w;
        acc2[2][0]+=a.z*w.x; acc2[2][1]+=a.z*w.y; acc2[2][2]+=a.z*w.z; acc2[2][3]+=a.z*w.w;
        acc2[3][0]+=a.w*w.x; acc2[3][1]+=a.w*w.y; acc2[3][2]+=a.w*w.z; acc2[3][3]+=a.w*w.w;
    }
    float4 qv = *(float4*)&qs[tc*4];
    float4 kv = *(float4*)&ks_[tc*4];
    #pragma unroll
    for (int i = 0; i < 4; i++) {
        int row = row0 + r0 + i;
        *(float4*)&g_xp2[row*CC + tc*4] = make_float4(acc2[i][0], acc2[i][1], acc2[i][2], acc2[i][3]);
        float pq = acc2[i][0]*qv.x + acc2[i][1]*qv.y + acc2[i][2]*qv.z + acc2[i][3]*qv.w;
        float pk = acc2[i][0]*kv.x + acc2[i][1]*kv.y + acc2[i][2]*kv.z + acc2[i][3]*kv.w;
        #pragma unroll
        for (int o = 8; o; o >>= 1) {
            pq += __shfl_down_sync(0xffffffffu, pq, o, 16);
            pk += __shfl_down_sync(0xffffffffu, pk, o, 16);
        }
        if (tc == 0) { redq[tg*4 + i] = pq; redk[tg*4 + i] = pk; }
    }
    __syncthreads();
    if (tid < 64) {
        g_asrc2[row0 + tid] = redq[tid];
        g_adst2[row0 + tid] = redk[tid];
    }
}

// ---------------- final output ----------------------------------------------
__global__ void out2_kernel(const float* __restrict__ ow, const float* __restrict__ ob,
                            float* __restrict__ yout) {
    extern __shared__ __align__(16) float sm[];
    float* ows  = sm;
    float* xs_t = ows + 2*CC*CC;
    float* as_t = xs_t + CC*XSTRIDE;
    __shared__ float obi[CC];
    int tid = threadIdx.x;
    for (int i = tid; i < 2*CC*CC; i += 256) {
        int k = i >> 6, c = i & 63;
        int pk = (k < CC) ? ilv(k) : CC + ilv(k - CC);
        ows[pk*CC + ilv(c)] = ow[i];
    }
    if (tid < CC) obi[tid] = ob[unilv(tid)];
    int row0 = blockIdx.x * 64;
    for (int i = tid*4; i < 64*CC; i += 1024) {
        int r = i >> 6, p0 = i & 63;
        float4 v = *(const float4*)&g_xp2[row0*CC + i];
        xs_t[(p0+0)*XSTRIDE + r] = v.x;
        xs_t[(p0+1)*XSTRIDE + r] = v.y;
        xs_t[(p0+2)*XSTRIDE + r] = v.z;
        xs_t[(p0+3)*XSTRIDE + r] = v.w;
        float4 u = *(const float4*)&g_aggr[row0*CC + i];
        as_t[(p0+0)*XSTRIDE + r] = u.x;
        as_t[(p0+1)*XSTRIDE + r] = u.y;
        as_t[(p0+2)*XSTRIDE + r] = u.z;
        as_t[(p0+3)*XSTRIDE + r] = u.w;
    }
    __syncthreads();
    int tc = tid & 15, tg = tid >> 4;
    int r0 = tg * 4;
    float acc[4][4];
    {
        float4 bv = *(float4*)&obi[tc*4];
        #pragma unroll
        for (int i = 0; i < 4; i++) { acc[i][0]=bv.x; acc[i][1]=bv.y; acc[i][2]=bv.z; acc[i][3]=bv.w; }
    }
    #pragma unroll 16
    for (int kk = 0; kk < CC; kk++) {
        float4 w = *(float4*)&ows[kk*CC + tc*4];
        float4 a = *(float4*)&xs_t[kk*XSTRIDE + r0];
        acc[0][0]+=a.x*w.x; acc[0][1]+=a.x*w.y; acc[0][2]+=a.x*w.z; acc[0][3]+=a.x*w.w;
        acc[1][0]+=a.y*w.x; acc[1][1]+=a.y*w.y; acc[1][2]+=a.y*w.z; acc[1][3]+=a.y*w.w;
        acc[2][0]+=a.z*w.x; acc[2][1]+=a.z*w.y; acc[2][2]+=a.z*w.z; acc[2][3]+=a.z*w.w;
        acc[3][0]+=a.w*w.x; acc[3][1]+=a.w*w.y; acc[3][2]+=a.w*w.z; acc[3][3]+=a.w*w.w;
    }
    #pragma unroll 16
    for (int kk = 0; kk < CC; kk++) {
        float4 w = *(float4*)&ows[(CC+kk)*CC + tc*4];
        float4 a = *(float4*)&as_t[kk*XSTRIDE + r0];
        acc[0][0]+=a.x*w.x; acc[0][1]+=a.x*w.y; acc[0][2]+=a.x*w.z; acc[0][3]+=a.x*w.w;
        acc[1][0]+=a.y*w.x; acc[1][1]+=a.y*w.y; acc[1][2]+=a.y*w.z; acc[1][3]+=a.y*w.w;
        acc[2][0]+=a.z*w.x; acc[2][1]+=a.z*w.y; acc[2][2]+=a.z*w.z; acc[2][3]+=a.z*w.w;
        acc[3][0]+=a.w*w.x; acc[3][1]+=a.w*w.y; acc[3][2]+=a.w*w.z; acc[3][3]+=a.w*w.w;
    }
    #pragma unroll
    for (int i = 0; i < 4; i++) {
        int row = row0 + r0 + i;
        #pragma unroll
        for (int j = 0; j < 4; j++) {
            int p = tc*4 + j;
            float v = xs_t[p*XSTRIDE + (r0+i)] + acc[i][j];
            yout[row*CC + unilv(p)] = (v > 0.f) ? v : 0.01f * v;
        }
    }
}

// ---------------- host orchestration ----------------------------------------
extern "C" void kernel_launch(void* const* d_in, const int* in_sizes, int n_in,
                              void* d_out, int out_size) {
    const float* X   = (const float*)d_in[0];
    const int*   ei  = (const int*)  d_in[1];
    const float* ea  = (const float*)d_in[2];
    const float* wn1 = (const float*)d_in[3];
    const float* we1 = (const float*)d_in[4];
    const float* q1  = (const float*)d_in[5];
    const float* k1  = (const float*)d_in[6];
    const float* aw1 = (const float*)d_in[7];
    const float* ab1 = (const float*)d_in[8];
    const float* ow1 = (const float*)d_in[9];
    const float* ob1 = (const float*)d_in[10];
    const float* wn2 = (const float*)d_in[11];
    const float* we2 = (const float*)d_in[12];
    const float* q2  = (const float*)d_in[13];
    const float* k2  = (const float*)d_in[14];
    const float* aw2 = (const float*)d_in[15];
    const float* ab2 = (const float*)d_in[16];
    const float* ow2 = (const float*)d_in[17];
    const float* ob2 = (const float*)d_in[18];

    float *xp1, *xp2, *asrc1, *adst1, *asrc2, *adst2, *aggr;
    cudaGetSymbolAddress((void**)&xp1,   g_xp1);
    cudaGetSymbolAddress((void**)&xp2,   g_xp2);
    cudaGetSymbolAddress((void**)&asrc1, g_asrc1);
    cudaGetSymbolAddress((void**)&adst1, g_adst1);
    cudaGetSymbolAddress((void**)&asrc2, g_asrc2);
    cudaGetSymbolAddress((void**)&adst2, g_adst2);
    cudaGetSymbolAddress((void**)&aggr,  g_aggr);

    const int MID_SMEM = (2*CC*CC + CC*CC + 3*CC*XSTRIDE) * 4;
    const int OUT_SMEM = (2*CC*CC + 2*CC*XSTRIDE) * 4;
    static bool attr_done = false;
    if (!attr_done) {
        cudaFuncSetAttribute(mid_kernel,  cudaFuncAttributeMaxDynamicSharedMemorySize, MID_SMEM);
        cudaFuncSetAttribute(out2_kernel, cudaFuncAttributeMaxDynamicSharedMemorySize, OUT_SMEM);
        attr_done = true;
    }

    prep_both_kernel<<<42, 256>>>(q1, k1, aw1, ab1, we1, q2, k2, aw2, ab2, we2);
    count_kernel<<<(EE + 255)/256, 256>>>(ei);
    scan_kernel<<<1, 1024>>>();
    xform1_kernel<<<NR/64, 256>>>(X, wn1);            // probe slot (idx 3)
    scatter_kernel<<<(EE + 255)/256, 256>>>(ei);
    escal_kernel<<<EE/256, 256>>>(ea);
    aggr_kernel<<<NN/8, 256>>>(xp1, asrc1, adst1, aggr, we1, ea, 0);
    mid_kernel<<<NR/64, 256, MID_SMEM>>>(ow1, ob1, wn2);
    aggr_kernel<<<NN/8, 256>>>(xp2, asrc2, adst2, aggr, we2, ea, 1);
    out2_kernel<<<NR/64, 256, OUT_SMEM>>>(ow2, ob2, (float*)d_out);
}

// round 6
// speedup vs baseline: 1.3134x; 1.0068x over previous
#include <cuda_runtime.h>
#include <math_constants.h>

#define NN 10000
#define BB 4
#define EE 160000
#define CC 64
#define CE 16
#define NR (NN*BB)          // 40000 rows
#define XSTRIDE 68          // padded row stride for transposed activation tiles

// INTERLEAVED channel layout for node tensors: channel c of row r lives at
// [r*64 + ilv(c)], ilv(c) = (c&31)*2 + (c>>5); unilv(p) = (p>>1) + (p&1)*32.
__device__ float  g_xp1[NR*CC];
__device__ float  g_xp2[NR*CC];
__device__ float  g_aggr[NR*CC];
__device__ float  g_asrc1[NR], g_adst1[NR];
__device__ float  g_asrc2[NR], g_adst2[NR];
__device__ float  g_qaw[2][CC], g_kaw[2][CC], g_wea[2][CE];
__device__ float  g_abv[2];
__device__ float2 g_esc[EE];         // per-edge attention scalar, both layers
__device__ int  g_deg[NN];
__device__ int  g_off[NN+1];
__device__ int  g_cur[NN];
__device__ int2 g_lst[EE];           // {edge id, src node}

__device__ __forceinline__ float sigmoidf(float x) {
    return 1.0f / (1.0f + __expf(-x));
}
__device__ __forceinline__ int ilv(int c)   { return (c & 31) * 2 + (c >> 5); }
__device__ __forceinline__ int unilv(int p) { return (p >> 1) + (p & 1) * 32; }

// ---------------- prep: fold attention weights (both layers) + zero deg ----
__global__ void prep_both_kernel(const float* q1, const float* k1, const float* aw1,
                                 const float* ab1, const float* we1,
                                 const float* q2, const float* k2, const float* aw2,
                                 const float* ab2, const float* we2) {
    int tid = threadIdx.x;
    if (blockIdx.x >= 2) {
        int i = (blockIdx.x - 2) * 256 + tid;
        if (i < NN) g_deg[i] = 0;
        return;
    }
    int layer = blockIdx.x;
    const float* q  = layer ? q2  : q1;
    const float* k  = layer ? k2  : k1;
    const float* aw = layer ? aw2 : aw1;
    const float* ab = layer ? ab2 : ab1;
    const float* we = layer ? we2 : we1;
    int w = tid >> 5, lane = tid & 31;
    float awq_lo = aw[lane],        awq_hi = aw[32 + lane];
    float awk_lo = aw[64 + lane],   awk_hi = aw[96 + lane];
    float aw3_lo = aw[128 + lane],  aw3_hi = aw[160 + lane];
    #pragma unroll
    for (int i = 0; i < 8; i++) {
        int row = w * 8 + i;
        float sq = q[row*CC + lane] * awq_lo + q[row*CC + 32 + lane] * awq_hi;
        float sk = k[row*CC + lane] * awk_lo + k[row*CC + 32 + lane] * awk_hi;
        #pragma unroll
        for (int o = 16; o; o >>= 1) {
            sq += __shfl_down_sync(0xffffffffu, sq, o);
            sk += __shfl_down_sync(0xffffffffu, sk, o);
        }
        if (lane == 0) { g_qaw[layer][row] = sq; g_kaw[layer][row] = sk; }
    }
    #pragma unroll
    for (int i = 0; i < 2; i++) {
        int row = w * 2 + i;
        float s = we[row*CC + lane] * aw3_lo + we[row*CC + 32 + lane] * aw3_hi;
        #pragma unroll
        for (int o = 16; o; o >>= 1) s += __shfl_down_sync(0xffffffffu, s, o);
        if (lane == 0) g_wea[layer][row] = s;
    }
    if (tid == 0) g_abv[layer] = ab[0];
}

// ---------------- CSR build -------------------------------------------------
__global__ void count_kernel(const int* __restrict__ ei) {
    int e = blockIdx.x * 256 + threadIdx.x;
    if (e < EE) atomicAdd(&g_deg[ei[EE + e]], 1);
}
__global__ void scan_kernel() {
    __shared__ int s[1024];
    const int CH = (NN + 1023) / 1024;
    int t = threadIdx.x;
    int base = t * CH;
    int local[CH];
    int sum = 0;
    #pragma unroll
    for (int i = 0; i < CH; i++) {
        local[i] = sum;
        if (base + i < NN) sum += g_deg[base + i];
    }
    s[t] = sum;
    __syncthreads();
    for (int off = 1; off < 1024; off <<= 1) {
        int v = (t >= off) ? s[t - off] : 0;
        __syncthreads();
        s[t] += v;
        __syncthreads();
    }
    int excl = (t == 0) ? 0 : s[t - 1];
    #pragma unroll
    for (int i = 0; i < CH; i++) {
        if (base + i < NN) {
            int o = excl + local[i];
            g_off[base + i] = o;
            g_cur[base + i] = o;
        }
    }
    if (t == 1023) g_off[NN] = s[1023];
}

// ---------------- scatter + per-edge attention scalars (fused) -------------
__global__ void scatter_escal_kernel(const int* __restrict__ ei,
                                     const float* __restrict__ eattr) {
    __shared__ float w1[CE], w2[CE];
    __shared__ float ab0, ab1;
    int tid = threadIdx.x;
    if (tid < CE) { w1[tid] = g_wea[0][tid]; w2[tid] = g_wea[1][tid]; }
    if (tid == 0) { ab0 = g_abv[0]; ab1 = g_abv[1]; }
    __syncthreads();
    int e = blockIdx.x * 256 + tid;
    int src = ei[e];
    int dst = ei[EE + e];
    int pos = atomicAdd(&g_cur[dst], 1);
    g_lst[pos] = make_int2(e, src);
    const float4* p = (const float4*)(eattr + (size_t)e * CE);
    float4 A = p[0], B = p[1], C = p[2], D = p[3];
    float a[16] = {A.x,A.y,A.z,A.w, B.x,B.y,B.z,B.w, C.x,C.y,C.z,C.w, D.x,D.y,D.z,D.w};
    float s1 = 0.f, s2 = 0.f;
    #pragma unroll
    for (int j = 0; j < CE; j++) { s1 += a[j]*w1[j]; s2 += a[j]*w2[j]; }
    g_esc[e] = make_float2(s1 + ab0, s2 + ab1);
}

// ---------------- layer-1 transform: transposed-x register-tiled GEMM ------
__global__ void xform1_kernel(const float* __restrict__ x, const float* __restrict__ wn) {
    __shared__ __align__(16) float ws[CC*CC];         // [k][interleaved c]
    __shared__ __align__(16) float xs_t[CC*XSTRIDE];  // [k][row]
    __shared__ float qs[CC], ks_[CC];
    __shared__ float redq[64], redk[64];
    int tid = threadIdx.x;
    for (int i = tid; i < CC*CC; i += 256) {
        int kk = i >> 6, c = i & 63;
        ws[kk*CC + ilv(c)] = wn[i];
    }
    if (tid < CC) { qs[tid] = g_qaw[0][unilv(tid)]; ks_[tid] = g_kaw[0][unilv(tid)]; }
    int row0 = blockIdx.x * 64;
    for (int i = tid*4; i < 64*CC; i += 1024) {
        float4 v = *(const float4*)&x[row0*CC + i];
        int r = i >> 6, c0 = i & 63;
        xs_t[(c0+0)*XSTRIDE + r] = v.x;
        xs_t[(c0+1)*XSTRIDE + r] = v.y;
        xs_t[(c0+2)*XSTRIDE + r] = v.z;
        xs_t[(c0+3)*XSTRIDE + r] = v.w;
    }
    __syncthreads();
    int tc = tid & 15, tg = tid >> 4;
    int r0 = tg * 4;
    float acc[4][4] = {};
    #pragma unroll 16
    for (int kk = 0; kk < CC; kk++) {
        float4 w = *(float4*)&ws[kk*CC + tc*4];
        float4 a = *(float4*)&xs_t[kk*XSTRIDE + r0];
        acc[0][0]+=a.x*w.x; acc[0][1]+=a.x*w.y; acc[0][2]+=a.x*w.z; acc[0][3]+=a.x*w.w;
        acc[1][0]+=a.y*w.x; acc[1][1]+=a.y*w.y; acc[1][2]+=a.y*w.z; acc[1][3]+=a.y*w.w;
        acc[2][0]+=a.z*w.x; acc[2][1]+=a.z*w.y; acc[2][2]+=a.z*w.z; acc[2][3]+=a.z*w.w;
        acc[3][0]+=a.w*w.x; acc[3][1]+=a.w*w.y; acc[3][2]+=a.w*w.z; acc[3][3]+=a.w*w.w;
    }
    float4 qv = *(float4*)&qs[tc*4];
    float4 kv = *(float4*)&ks_[tc*4];
    #pragma unroll
    for (int i = 0; i < 4; i++) {
        int row = row0 + r0 + i;
        *(float4*)&g_xp1[row*CC + tc*4] = make_float4(acc[i][0], acc[i][1], acc[i][2], acc[i][3]);
        float pq = acc[i][0]*qv.x + acc[i][1]*qv.y + acc[i][2]*qv.z + acc[i][3]*qv.w;
        float pk = acc[i][0]*kv.x + acc[i][1]*kv.y + acc[i][2]*kv.z + acc[i][3]*kv.w;
        #pragma unroll
        for (int o = 8; o; o >>= 1) {
            pq += __shfl_down_sync(0xffffffffu, pq, o, 16);
            pk += __shfl_down_sync(0xffffffffu, pk, o, 16);
        }
        if (tc == 0) { redq[tg*4 + i] = pq; redk[tg*4 + i] = pk; }
    }
    __syncthreads();
    if (tid < 64) {
        g_asrc1[row0 + tid] = redq[tid];
        g_adst1[row0 + tid] = redk[tid];
    }
}

// ---------------- segment max: gate weights in REGISTERS, no smem ----------
// one warp per node, block = 256 (8 nodes)
__global__ void aggr_kernel(const float* __restrict__ xp, const float* __restrict__ asrcp,
                            const float* __restrict__ adstp, float* __restrict__ aggrp,
                            const float* __restrict__ we, const float* __restrict__ eattr,
                            int layer) {
    int lane = threadIdx.x & 31;
    // loop-invariant gate weights: lane handles interleaved channels (lane, lane+32)
    float2 wreg[CE];
    #pragma unroll
    for (int j = 0; j < CE; j++)
        wreg[j] = make_float2(__ldg(&we[j*CC + lane]), __ldg(&we[j*CC + 32 + lane]));
    int n = blockIdx.x * 8 + (threadIdx.x >> 5);
    int beg = g_off[n], end = g_off[n+1];
    float4 ad = *(const float4*)&adstp[n*4];
    float mx0[BB], mx1[BB];
    #pragma unroll
    for (int b = 0; b < BB; b++) { mx0[b] = -CUDART_INF_F; mx1[b] = -CUDART_INF_F; }
    int2 nx = (beg < end) ? __ldg(&g_lst[beg]) : make_int2(0, 0);
    for (int i = beg; i < end; i++) {
        int e = nx.x, src = nx.y;
        if (i + 1 < end) nx = __ldg(&g_lst[i+1]);
        const float4* p4 = (const float4*)(eattr + (size_t)e * CE);
        float4 A = p4[0], B = p4[1], Cv = p4[2], D = p4[3];
        float2 e2 = __ldg(&g_esc[e]);
        float esc = layer ? e2.y : e2.x;
        float4 as = *(const float4*)&asrcp[src*4];
        float av[16] = {A.x,A.y,A.z,A.w, B.x,B.y,B.z,B.w, Cv.x,Cv.y,Cv.z,Cv.w, D.x,D.y,D.z,D.w};
        float gx = 0.f, gy = 0.f, hx = 0.f, hy = 0.f;
        #pragma unroll
        for (int j = 0; j < CE; j += 2) {
            gx += av[j]  * wreg[j].x;   gy += av[j]  * wreg[j].y;
            hx += av[j+1]* wreg[j+1].x; hy += av[j+1]* wreg[j+1].y;
        }
        float gA = sigmoidf(gx + hx);
        float gB = sigmoidf(gy + hy);
        float attv[BB];
        attv[0] = sigmoidf(as.x + ad.x + esc);
        attv[1] = sigmoidf(as.y + ad.y + esc);
        attv[2] = sigmoidf(as.z + ad.z + esc);
        attv[3] = sigmoidf(as.w + ad.w + esc);
        #pragma unroll
        for (int b = 0; b < BB; b++) {
            float2 x = *(const float2*)&xp[(src*BB + b)*CC + lane*2];
            mx0[b] = fmaxf(mx0[b], attv[b] * x.x * gA);
            mx1[b] = fmaxf(mx1[b], attv[b] * x.y * gB);
        }
    }
    bool empty = (beg == end);
    #pragma unroll
    for (int b = 0; b < BB; b++) {
        float2 o = empty ? make_float2(0.f, 0.f) : make_float2(mx0[b], mx1[b]);
        *(float2*)&aggrp[(n*BB + b)*CC + lane*2] = o;
    }
}

// ---------------- fused: layer1 output + layer2 transform ------------------
__global__ void mid_kernel(const float* __restrict__ ow, const float* __restrict__ ob,
                           const float* __restrict__ wn2) {
    extern __shared__ __align__(16) float sm[];
    float* ows  = sm;                        // 8192
    float* wns  = ows + 2*CC*CC;             // 4096
    float* xs_t = wns + CC*CC;               // CC*XSTRIDE
    float* as_t = xs_t + CC*XSTRIDE;
    float* ys_t = as_t + CC*XSTRIDE;
    __shared__ float obi[CC], qs[CC], ks_[CC];
    __shared__ float redq[64], redk[64];
    int tid = threadIdx.x;
    for (int i = tid; i < 2*CC*CC; i += 256) {
        int k = i >> 6, c = i & 63;
        int pk = (k < CC) ? ilv(k) : CC + ilv(k - CC);
        ows[pk*CC + ilv(c)] = ow[i];
    }
    for (int i = tid; i < CC*CC; i += 256) {
        int k = i >> 6, c = i & 63;
        wns[ilv(k)*CC + ilv(c)] = wn2[i];
    }
    if (tid < CC) {
        int c = unilv(tid);
        obi[tid] = ob[c];
        qs[tid]  = g_qaw[1][c];
        ks_[tid] = g_kaw[1][c];
    }
    int row0 = blockIdx.x * 64;
    for (int i = tid*4; i < 64*CC; i += 1024) {
        int r = i >> 6, p0 = i & 63;
        float4 v = *(const float4*)&g_xp1[row0*CC + i];
        xs_t[(p0+0)*XSTRIDE + r] = v.x;
        xs_t[(p0+1)*XSTRIDE + r] = v.y;
        xs_t[(p0+2)*XSTRIDE + r] = v.z;
        xs_t[(p0+3)*XSTRIDE + r] = v.w;
        float4 u = *(const float4*)&g_aggr[row0*CC + i];
        as_t[(p0+0)*XSTRIDE + r] = u.x;
        as_t[(p0+1)*XSTRIDE + r] = u.y;
        as_t[(p0+2)*XSTRIDE + r] = u.z;
        as_t[(p0+3)*XSTRIDE + r] = u.w;
    }
    __syncthreads();
    int tc = tid & 15, tg = tid >> 4;
    int r0 = tg * 4;
    float acc[4][4];
    {
        float4 bv = *(float4*)&obi[tc*4];
        #pragma unroll
        for (int i = 0; i < 4; i++) { acc[i][0]=bv.x; acc[i][1]=bv.y; acc[i][2]=bv.z; acc[i][3]=bv.w; }
    }
    #pragma unroll 16
    for (int kk = 0; kk < CC; kk++) {
        float4 w = *(float4*)&ows[kk*CC + tc*4];
        float4 a = *(float4*)&xs_t[kk*XSTRIDE + r0];
        acc[0][0]+=a.x*w.x; acc[0][1]+=a.x*w.y; acc[0][2]+=a.x*w.z; acc[0][3]+=a.x*w.w;
        acc[1][0]+=a.y*w.x; acc[1][1]+=a.y*w.y; acc[1][2]+=a.y*w.z; acc[1][3]+=a.y*w.w;
        acc[2][0]+=a.z*w.x; acc[2][1]+=a.z*w.y; acc[2][2]+=a.z*w.z; acc[2][3]+=a.z*w.w;
        acc[3][0]+=a.w*w.x; acc[3][1]+=a.w*w.y; acc[3][2]+=a.w*w.z; acc[3][3]+=a.w*w.w;
    }
    #pragma unroll 16
    for (int kk = 0; kk < CC; kk++) {
        float4 w = *(float4*)&ows[(CC+kk)*CC + tc*4];
        float4 a = *(float4*)&as_t[kk*XSTRIDE + r0];
        acc[0][0]+=a.x*w.x; acc[0][1]+=a.x*w.y; acc[0][2]+=a.x*w.z; acc[0][3]+=a.x*w.w;
        acc[1][0]+=a.y*w.x; acc[1][1]+=a.y*w.y; acc[1][2]+=a.y*w.z; acc[1][3]+=a.y*w.w;
        acc[2][0]+=a.z*w.x; acc[2][1]+=a.z*w.y; acc[2][2]+=a.z*w.z; acc[2][3]+=a.z*w.w;
        acc[3][0]+=a.w*w.x; acc[3][1]+=a.w*w.y; acc[3][2]+=a.w*w.z; acc[3][3]+=a.w*w.w;
    }
    #pragma unroll
    for (int i = 0; i < 4; i++) {
        #pragma unroll
        for (int j = 0; j < 4; j++) {
            int p = tc*4 + j, r = r0 + i;
            float v = xs_t[p*XSTRIDE + r] + acc[i][j];
            ys_t[p*XSTRIDE + r] = (v > 0.f) ? v : 0.01f * v;
        }
    }
    __syncthreads();
    float acc2[4][4] = {};
    #pragma unroll 16
    for (int kk = 0; kk < CC; kk++) {
        float4 w = *(float4*)&wns[kk*CC + tc*4];
        float4 a = *(float4*)&ys_t[kk*XSTRIDE + r0];
        acc2[0][0]+=a.x*w.x; acc2[0][1]+=a.x*w.y; acc2[0][2]+=a.x*w.z; acc2[0][3]+=a.x*w.w;
        acc2[1][0]+=a.y*w.x; acc2[1][1]+=a.y*w.y; acc2[1][2]+=a.y*w.z; acc2[1][3]+=a.y*w.w;
        acc2[2][0]+=a.z*w.x; acc2[2][1]+=a.z*w.y; acc2[2][2]+=a.z*w.z; acc2[2][3]+=a.z*w.w;
        acc2[3][0]+=a.w*w.x; acc2[3][1]+=a.w*w.y; acc2[3][2]+=a.w*w.z; acc2[3][3]+=a.w*w.w;
    }
    float4 qv = *(float4*)&qs[tc*4];
    float4 kv = *(float4*)&ks_[tc*4];
    #pragma unroll
    for (int i = 0; i < 4; i++) {
        int row = row0 + r0 + i;
        *(float4*)&g_xp2[row*CC + tc*4] = make_float4(acc2[i][0], acc2[i][1], acc2[i][2], acc2[i][3]);
        float pq = acc2[i][0]*qv.x + acc2[i][1]*qv.y + acc2[i][2]*qv.z + acc2[i][3]*qv.w;
        float pk = acc2[i][0]*kv.x + acc2[i][1]*kv.y + acc2[i][2]*kv.z + acc2[i][3]*kv.w;
        #pragma unroll
        for (int o = 8; o; o >>= 1) {
            pq += __shfl_down_sync(0xffffffffu, pq, o, 16);
            pk += __shfl_down_sync(0xffffffffu, pk, o, 16);
        }
        if (tc == 0) { redq[tg*4 + i] = pq; redk[tg*4 + i] = pk; }
    }
    __syncthreads();
    if (tid < 64) {
        g_asrc2[row0 + tid] = redq[tid];
        g_adst2[row0 + tid] = redk[tid];
    }
}

// ---------------- final output ----------------------------------------------
__global__ void out2_kernel(const float* __restrict__ ow, const float* __restrict__ ob,
                            float* __restrict__ yout) {
    extern __shared__ __align__(16) float sm[];
    float* ows  = sm;
    float* xs_t = ows + 2*CC*CC;
    float* as_t = xs_t + CC*XSTRIDE;
    __shared__ float obi[CC];
    int tid = threadIdx.x;
    for (int i = tid; i < 2*CC*CC; i += 256) {
        int k = i >> 6, c = i & 63;
        int pk = (k < CC) ? ilv(k) : CC + ilv(k - CC);
        ows[pk*CC + ilv(c)] = ow[i];
    }
    if (tid < CC) obi[tid] = ob[unilv(tid)];
    int row0 = blockIdx.x * 64;
    for (int i = tid*4; i < 64*CC; i += 1024) {
        int r = i >> 6, p0 = i & 63;
        float4 v = *(const float4*)&g_xp2[row0*CC + i];
        xs_t[(p0+0)*XSTRIDE + r] = v.x;
        xs_t[(p0+1)*XSTRIDE + r] = v.y;
        xs_t[(p0+2)*XSTRIDE + r] = v.z;
        xs_t[(p0+3)*XSTRIDE + r] = v.w;
        float4 u = *(const float4*)&g_aggr[row0*CC + i];
        as_t[(p0+0)*XSTRIDE + r] = u.x;
        as_t[(p0+1)*XSTRIDE + r] = u.y;
        as_t[(p0+2)*XSTRIDE + r] = u.z;
        as_t[(p0+3)*XSTRIDE + r] = u.w;
    }
    __syncthreads();
    int tc = tid & 15, tg = tid >> 4;
    int r0 = tg * 4;
    float acc[4][4];
    {
        float4 bv = *(float4*)&obi[tc*4];
        #pragma unroll
        for (int i = 0; i < 4; i++) { acc[i][0]=bv.x; acc[i][1]=bv.y; acc[i][2]=bv.z; acc[i][3]=bv.w; }
    }
    #pragma unroll 16
    for (int kk = 0; kk < CC; kk++) {
        float4 w = *(float4*)&ows[kk*CC + tc*4];
        float4 a = *(float4*)&xs_t[kk*XSTRIDE + r0];
        acc[0][0]+=a.x*w.x; acc[0][1]+=a.x*w.y; acc[0][2]+=a.x*w.z; acc[0][3]+=a.x*w.w;
        acc[1][0]+=a.y*w.x; acc[1][1]+=a.y*w.y; acc[1][2]+=a.y*w.z; acc[1][3]+=a.y*w.w;
        acc[2][0]+=a.z*w.x; acc[2][1]+=a.z*w.y; acc[2][2]+=a.z*w.z; acc[2][3]+=a.z*w.w;
        acc[3][0]+=a.w*w.x; acc[3][1]+=a.w*w.y; acc[3][2]+=a.w*w.z; acc[3][3]+=a.w*w.w;
    }
    #pragma unroll 16
    for (int kk = 0; kk < CC; kk++) {
        float4 w = *(float4*)&ows[(CC+kk)*CC + tc*4];
        float4 a = *(float4*)&as_t[kk*XSTRIDE + r0];
        acc[0][0]+=a.x*w.x; acc[0][1]+=a.x*w.y; acc[0][2]+=a.x*w.z; acc[0][3]+=a.x*w.w;
        acc[1][0]+=a.y*w.x; acc[1][1]+=a.y*w.y; acc[1][2]+=a.y*w.z; acc[1][3]+=a.y*w.w;
        acc[2][0]+=a.z*w.x; acc[2][1]+=a.z*w.y; acc[2][2]+=a.z*w.z; acc[2][3]+=a.z*w.w;
        acc[3][0]+=a.w*w.x; acc[3][1]+=a.w*w.y; acc[3][2]+=a.w*w.z; acc[3][3]+=a.w*w.w;
    }
    #pragma unroll
    for (int i = 0; i < 4; i++) {
        int row = row0 + r0 + i;
        #pragma unroll
        for (int j = 0; j < 4; j++) {
            int p = tc*4 + j;
            float v = xs_t[p*XSTRIDE + (r0+i)] + acc[i][j];
            yout[row*CC + unilv(p)] = (v > 0.f) ? v : 0.01f * v;
        }
    }
}

// ---------------- host orchestration ----------------------------------------
extern "C" void kernel_launch(void* const* d_in, const int* in_sizes, int n_in,
                              void* d_out, int out_size) {
    const float* X   = (const float*)d_in[0];
    const int*   ei  = (const int*)  d_in[1];
    const float* ea  = (const float*)d_in[2];
    const float* wn1 = (const float*)d_in[3];
    const float* we1 = (const float*)d_in[4];
    const float* q1  = (const float*)d_in[5];
    const float* k1  = (const float*)d_in[6];
    const float* aw1 = (const float*)d_in[7];
    const float* ab1 = (const float*)d_in[8];
    const float* ow1 = (const float*)d_in[9];
    const float* ob1 = (const float*)d_in[10];
    const float* wn2 = (const float*)d_in[11];
    const float* we2 = (const float*)d_in[12];
    const float* q2  = (const float*)d_in[13];
    const float* k2  = (const float*)d_in[14];
    const float* aw2 = (const float*)d_in[15];
    const float* ab2 = (const float*)d_in[16];
    const float* ow2 = (const float*)d_in[17];
    const float* ob2 = (const float*)d_in[18];

    float *xp1, *xp2, *asrc1, *adst1, *asrc2, *adst2, *aggr;
    cudaGetSymbolAddress((void**)&xp1,   g_xp1);
    cudaGetSymbolAddress((void**)&xp2,   g_xp2);
    cudaGetSymbolAddress((void**)&asrc1, g_asrc1);
    cudaGetSymbolAddress((void**)&adst1, g_adst1);
    cudaGetSymbolAddress((void**)&asrc2, g_asrc2);
    cudaGetSymbolAddress((void**)&adst2, g_adst2);
    cudaGetSymbolAddress((void**)&aggr,  g_aggr);

    const int MID_SMEM = (2*CC*CC + CC*CC + 3*CC*XSTRIDE) * 4;
    const int OUT_SMEM = (2*CC*CC + 2*CC*XSTRIDE) * 4;
    static bool attr_done = false;
    if (!attr_done) {
        cudaFuncSetAttribute(mid_kernel,  cudaFuncAttributeMaxDynamicSharedMemorySize, MID_SMEM);
        cudaFuncSetAttribute(out2_kernel, cudaFuncAttributeMaxDynamicSharedMemorySize, OUT_SMEM);
        attr_done = true;
    }

    prep_both_kernel<<<42, 256>>>(q1, k1, aw1, ab1, we1, q2, k2, aw2, ab2, we2);
    count_kernel<<<(EE + 255)/256, 256>>>(ei);
    scan_kernel<<<1, 1024>>>();
    xform1_kernel<<<NR/64, 256>>>(X, wn1);
    scatter_escal_kernel<<<EE/256, 256>>>(ei, ea);
    aggr_kernel<<<NN/8, 256>>>(xp1, asrc1, adst1, aggr, we1, ea, 0);   // probe slot (idx 5)
    mid_kernel<<<NR/64, 256, MID_SMEM>>>(ow1, ob1, wn2);
    aggr_kernel<<<NN/8, 256>>>(xp2, asrc2, adst2, aggr, we2, ea, 1);
    out2_kernel<<<NR/64, 256, OUT_SMEM>>>(ow2, ob2, (float*)d_out);
}

// round 7
// speedup vs baseline: 1.7574x; 1.3381x over previous
#include <cuda_runtime.h>
#include <math_constants.h>

#define NN 10000
#define BB 4
#define EE 160000
#define CC 64
#define CE 16
#define NR (NN*BB)          // 40000 rows
#define XSTRIDE 68          // padded row stride for transposed activation tiles

// INTERLEAVED channel layout for node tensors: channel c of row r lives at
// [r*64 + ilv(c)], ilv(c) = (c&31)*2 + (c>>5); unilv(p) = (p>>1) + (p&1)*32.
__device__ float  g_xp1[NR*CC];
__device__ float  g_xp2[NR*CC];
__device__ float  g_aggr[NR*CC];
__device__ float  g_asrc1[NR], g_adst1[NR];
__device__ float  g_asrc2[NR], g_adst2[NR];
__device__ float  g_qaw[2][CC], g_kaw[2][CC], g_wea[2][CE];
__device__ float  g_abv[2];
__device__ float2 g_esc[EE];         // per-edge attention scalar, both layers
__device__ int  g_deg[NN];           // zeroed at END of each run (and statically)
__device__ int  g_off[NN+1];
__device__ int  g_cur[NN];
__device__ int2 g_lst[EE];           // {edge id, src node}

__device__ __forceinline__ float sigmoidf(float x) {
    return 1.0f / (1.0f + __expf(-x));
}
__device__ __forceinline__ int ilv(int c)   { return (c & 31) * 2 + (c >> 5); }
__device__ __forceinline__ int unilv(int p) { return (p >> 1) + (p & 1) * 32; }

// ---------------- launch 0: fold attention weights + degree count ----------
// grid 625 x 256: blocks 0/1 fold weights for layer 0/1; ALL blocks count.
__global__ void prep_count_kernel(const int* __restrict__ ei,
                                  const float* q1, const float* k1, const float* aw1,
                                  const float* ab1, const float* we1,
                                  const float* q2, const float* k2, const float* aw2,
                                  const float* ab2, const float* we2) {
    int tid = threadIdx.x;
    if (blockIdx.x < 2) {
        int layer = blockIdx.x;
        const float* q  = layer ? q2  : q1;
        const float* k  = layer ? k2  : k1;
        const float* aw = layer ? aw2 : aw1;
        const float* ab = layer ? ab2 : ab1;
        const float* we = layer ? we2 : we1;
        int w = tid >> 5, lane = tid & 31;
        float awq_lo = aw[lane],        awq_hi = aw[32 + lane];
        float awk_lo = aw[64 + lane],   awk_hi = aw[96 + lane];
        float aw3_lo = aw[128 + lane],  aw3_hi = aw[160 + lane];
        #pragma unroll
        for (int i = 0; i < 8; i++) {
            int row = w * 8 + i;
            float sq = q[row*CC + lane] * awq_lo + q[row*CC + 32 + lane] * awq_hi;
            float sk = k[row*CC + lane] * awk_lo + k[row*CC + 32 + lane] * awk_hi;
            #pragma unroll
            for (int o = 16; o; o >>= 1) {
                sq += __shfl_down_sync(0xffffffffu, sq, o);
                sk += __shfl_down_sync(0xffffffffu, sk, o);
            }
            if (lane == 0) { g_qaw[layer][row] = sq; g_kaw[layer][row] = sk; }
        }
        #pragma unroll
        for (int i = 0; i < 2; i++) {
            int row = w * 2 + i;
            float s = we[row*CC + lane] * aw3_lo + we[row*CC + 32 + lane] * aw3_hi;
            #pragma unroll
            for (int o = 16; o; o >>= 1) s += __shfl_down_sync(0xffffffffu, s, o);
            if (lane == 0) g_wea[layer][row] = s;
        }
        if (tid == 0) g_abv[layer] = ab[0];
    }
    int e = blockIdx.x * 256 + tid;   // 625*256 = 160000 exactly
    atomicAdd(&g_deg[ei[EE + e]], 1);
}

// ---------------- launch 1: exclusive scan -> g_off / g_cur ----------------
__global__ void scan_kernel() {
    __shared__ int s[1024];
    const int CH = (NN + 1023) / 1024;
    int t = threadIdx.x;
    int base = t * CH;
    int local[CH];
    int sum = 0;
    #pragma unroll
    for (int i = 0; i < CH; i++) {
        local[i] = sum;
        if (base + i < NN) sum += g_deg[base + i];
    }
    s[t] = sum;
    __syncthreads();
    for (int off = 1; off < 1024; off <<= 1) {
        int v = (t >= off) ? s[t - off] : 0;
        __syncthreads();
        s[t] += v;
        __syncthreads();
    }
    int excl = (t == 0) ? 0 : s[t - 1];
    #pragma unroll
    for (int i = 0; i < CH; i++) {
        if (base + i < NN) {
            int o = excl + local[i];
            g_off[base + i] = o;
            g_cur[base + i] = o;
        }
    }
    if (t == 1023) g_off[NN] = s[1023];
}

// ---------------- launch 2: xform1 GEMM + CSR scatter + escal (fused) ------
// grid 625 x 256: each block does 64 node-rows of xp1 AND 256 edges of scatter.
__global__ void xform1_scatter_kernel(const float* __restrict__ x,
                                      const float* __restrict__ wn,
                                      const int* __restrict__ ei,
                                      const float* __restrict__ eattr) {
    __shared__ __align__(16) float ws[CC*CC];         // [k][interleaved c]
    __shared__ __align__(16) float xs_t[CC*XSTRIDE];  // [k][row]
    __shared__ float qs[CC], ks_[CC];
    __shared__ float redq[64], redk[64];
    __shared__ float w1[CE], w2[CE];
    __shared__ float ab0, ab1;
    int tid = threadIdx.x;
    for (int i = tid; i < CC*CC; i += 256) {
        int kk = i >> 6, c = i & 63;
        ws[kk*CC + ilv(c)] = wn[i];
    }
    if (tid < CC) { qs[tid] = g_qaw[0][unilv(tid)]; ks_[tid] = g_kaw[0][unilv(tid)]; }
    if (tid >= 64 && tid < 64 + CE) { w1[tid-64] = g_wea[0][tid-64]; w2[tid-64] = g_wea[1][tid-64]; }
    if (tid == 127) { ab0 = g_abv[0]; ab1 = g_abv[1]; }
    int row0 = blockIdx.x * 64;
    for (int i = tid*4; i < 64*CC; i += 1024) {
        float4 v = *(const float4*)&x[row0*CC + i];
        int r = i >> 6, c0 = i & 63;
        xs_t[(c0+0)*XSTRIDE + r] = v.x;
        xs_t[(c0+1)*XSTRIDE + r] = v.y;
        xs_t[(c0+2)*XSTRIDE + r] = v.z;
        xs_t[(c0+3)*XSTRIDE + r] = v.w;
    }
    __syncthreads();
    // ---- scatter + escal for this block's 256 edges ----
    {
        int e = blockIdx.x * 256 + tid;
        int src = ei[e];
        int dst = ei[EE + e];
        int pos = atomicAdd(&g_cur[dst], 1);
        g_lst[pos] = make_int2(e, src);
        const float4* p = (const float4*)(eattr + (size_t)e * CE);
        float4 A = p[0], B = p[1], C = p[2], D = p[3];
        float a[16] = {A.x,A.y,A.z,A.w, B.x,B.y,B.z,B.w, C.x,C.y,C.z,C.w, D.x,D.y,D.z,D.w};
        float s1 = 0.f, s2 = 0.f;
        #pragma unroll
        for (int j = 0; j < CE; j++) { s1 += a[j]*w1[j]; s2 += a[j]*w2[j]; }
        g_esc[e] = make_float2(s1 + ab0, s2 + ab1);
    }
    // ---- register-tiled GEMM: 64 rows x 64 cols ----
    int tc = tid & 15, tg = tid >> 4;
    int r0 = tg * 4;
    float acc[4][4] = {};
    #pragma unroll 16
    for (int kk = 0; kk < CC; kk++) {
        float4 w = *(float4*)&ws[kk*CC + tc*4];
        float4 a = *(float4*)&xs_t[kk*XSTRIDE + r0];
        acc[0][0]+=a.x*w.x; acc[0][1]+=a.x*w.y; acc[0][2]+=a.x*w.z; acc[0][3]+=a.x*w.w;
        acc[1][0]+=a.y*w.x; acc[1][1]+=a.y*w.y; acc[1][2]+=a.y*w.z; acc[1][3]+=a.y*w.w;
        acc[2][0]+=a.z*w.x; acc[2][1]+=a.z*w.y; acc[2][2]+=a.z*w.z; acc[2][3]+=a.z*w.w;
        acc[3][0]+=a.w*w.x; acc[3][1]+=a.w*w.y; acc[3][2]+=a.w*w.z; acc[3][3]+=a.w*w.w;
    }
    float4 qv = *(float4*)&qs[tc*4];
    float4 kv = *(float4*)&ks_[tc*4];
    #pragma unroll
    for (int i = 0; i < 4; i++) {
        int row = row0 + r0 + i;
        *(float4*)&g_xp1[row*CC + tc*4] = make_float4(acc[i][0], acc[i][1], acc[i][2], acc[i][3]);
        float pq = acc[i][0]*qv.x + acc[i][1]*qv.y + acc[i][2]*qv.z + acc[i][3]*qv.w;
        float pk = acc[i][0]*kv.x + acc[i][1]*kv.y + acc[i][2]*kv.z + acc[i][3]*kv.w;
        #pragma unroll
        for (int o = 8; o; o >>= 1) {
            pq += __shfl_down_sync(0xffffffffu, pq, o, 16);
            pk += __shfl_down_sync(0xffffffffu, pk, o, 16);
        }
        if (tc == 0) { redq[tg*4 + i] = pq; redk[tg*4 + i] = pk; }
    }
    __syncthreads();
    if (tid < 64) {
        g_asrc1[row0 + tid] = redq[tid];
        g_adst1[row0 + tid] = redk[tid];
    }
}

// ---------------- launch 3 (PROBE) / 5: segment max ------------------------
// one warp per node, block = 256 (8 nodes); att via lane-quad shfl (6 MUFU/edge)
__global__ void aggr_kernel(const float* __restrict__ xp, const float* __restrict__ asrcp,
                            const float* __restrict__ adstp, float* __restrict__ aggrp,
                            const float* __restrict__ we, const float* __restrict__ eattr,
                            int layer) {
    int lane = threadIdx.x & 31;
    int lb = lane & 3;
    float2 wreg[CE];
    #pragma unroll
    for (int j = 0; j < CE; j++)
        wreg[j] = make_float2(__ldg(&we[j*CC + lane]), __ldg(&we[j*CC + 32 + lane]));
    int n = blockIdx.x * 8 + (threadIdx.x >> 5);
    int beg = g_off[n], end = g_off[n+1];
    float ad_l = adstp[n*4 + lb];
    float mx0[BB], mx1[BB];
    #pragma unroll
    for (int b = 0; b < BB; b++) { mx0[b] = -CUDART_INF_F; mx1[b] = -CUDART_INF_F; }
    int2 nx = (beg < end) ? __ldg(&g_lst[beg]) : make_int2(0, 0);
    for (int i = beg; i < end; i++) {
        int e = nx.x, src = nx.y;
        if (i + 1 < end) nx = __ldg(&g_lst[i+1]);
        const float4* p4 = (const float4*)(eattr + (size_t)e * CE);
        float4 A = p4[0], B = p4[1], Cv = p4[2], D = p4[3];
        float2 e2 = __ldg(&g_esc[e]);
        float esc = layer ? e2.y : e2.x;
        float as_l = __ldg(&asrcp[src*4 + lb]);
        // lane-quad att: each lane computes sigma for batch (lane&3), broadcast w/ width-4 shfl
        float att_l = sigmoidf(as_l + ad_l + esc);
        float attv[BB];
        #pragma unroll
        for (int b = 0; b < BB; b++) attv[b] = __shfl_sync(0xffffffffu, att_l, b, 4);
        float av[16] = {A.x,A.y,A.z,A.w, B.x,B.y,B.z,B.w, Cv.x,Cv.y,Cv.z,Cv.w, D.x,D.y,D.z,D.w};
        float gx = 0.f, gy = 0.f, hx = 0.f, hy = 0.f;
        #pragma unroll
        for (int j = 0; j < CE; j += 2) {
            gx += av[j]  * wreg[j].x;   gy += av[j]  * wreg[j].y;
            hx += av[j+1]* wreg[j+1].x; hy += av[j+1]* wreg[j+1].y;
        }
        float gA = sigmoidf(gx + hx);
        float gB = sigmoidf(gy + hy);
        #pragma unroll
        for (int b = 0; b < BB; b++) {
            float2 x = *(const float2*)&xp[(src*BB + b)*CC + lane*2];
            mx0[b] = fmaxf(mx0[b], attv[b] * x.x * gA);
            mx1[b] = fmaxf(mx1[b], attv[b] * x.y * gB);
        }
    }
    bool empty = (beg == end);
    #pragma unroll
    for (int b = 0; b < BB; b++) {
        float2 o = empty ? make_float2(0.f, 0.f) : make_float2(mx0[b], mx1[b]);
        *(float2*)&aggrp[(n*BB + b)*CC + lane*2] = o;
    }
}

// ---------------- launch 4: fused layer1 output + layer2 transform ---------
__global__ void mid_kernel(const float* __restrict__ ow, const float* __restrict__ ob,
                           const float* __restrict__ wn2) {
    extern __shared__ __align__(16) float sm[];
    float* ows  = sm;
    float* wns  = ows + 2*CC*CC;
    float* xs_t = wns + CC*CC;
    float* as_t = xs_t + CC*XSTRIDE;
    float* ys_t = as_t + CC*XSTRIDE;
    __shared__ float obi[CC], qs[CC], ks_[CC];
    __shared__ float redq[64], redk[64];
    int tid = threadIdx.x;
    for (int i = tid; i < 2*CC*CC; i += 256) {
        int k = i >> 6, c = i & 63;
        int pk = (k < CC) ? ilv(k) : CC + ilv(k - CC);
        ows[pk*CC + ilv(c)] = ow[i];
    }
    for (int i = tid; i < CC*CC; i += 256) {
        int k = i >> 6, c = i & 63;
        wns[ilv(k)*CC + ilv(c)] = wn2[i];
    }
    if (tid < CC) {
        int c = unilv(tid);
        obi[tid] = ob[c];
        qs[tid]  = g_qaw[1][c];
        ks_[tid] = g_kaw[1][c];
    }
    int row0 = blockIdx.x * 64;
    for (int i = tid*4; i < 64*CC; i += 1024) {
        int r = i >> 6, p0 = i & 63;
        float4 v = *(const float4*)&g_xp1[row0*CC + i];
        xs_t[(p0+0)*XSTRIDE + r] = v.x;
        xs_t[(p0+1)*XSTRIDE + r] = v.y;
        xs_t[(p0+2)*XSTRIDE + r] = v.z;
        xs_t[(p0+3)*XSTRIDE + r] = v.w;
        float4 u = *(const float4*)&g_aggr[row0*CC + i];
        as_t[(p0+0)*XSTRIDE + r] = u.x;
        as_t[(p0+1)*XSTRIDE + r] = u.y;
        as_t[(p0+2)*XSTRIDE + r] = u.z;
        as_t[(p0+3)*XSTRIDE + r] = u.w;
    }
    __syncthreads();
    int tc = tid & 15, tg = tid >> 4;
    int r0 = tg * 4;
    float acc[4][4];
    {
        float4 bv = *(float4*)&obi[tc*4];
        #pragma unroll
        for (int i = 0; i < 4; i++) { acc[i][0]=bv.x; acc[i][1]=bv.y; acc[i][2]=bv.z; acc[i][3]=bv.w; }
    }
    #pragma unroll 16
    for (int kk = 0; kk < CC; kk++) {
        float4 w = *(float4*)&ows[kk*CC + tc*4];
        float4 a = *(float4*)&xs_t[kk*XSTRIDE + r0];
        acc[0][0]+=a.x*w.x; acc[0][1]+=a.x*w.y; acc[0][2]+=a.x*w.z; acc[0][3]+=a.x*w.w;
        acc[1][0]+=a.y*w.x; acc[1][1]+=a.y*w.y; acc[1][2]+=a.y*w.z; acc[1][3]+=a.y*w.w;
        acc[2][0]+=a.z*w.x; acc[2][1]+=a.z*w.y; acc[2][2]+=a.z*w.z; acc[2][3]+=a.z*w.w;
        acc[3][0]+=a.w*w.x; acc[3][1]+=a.w*w.y; acc[3][2]+=a.w*w.z; acc[3][3]+=a.w*w.w;
    }
    #pragma unroll 16
    for (int kk = 0; kk < CC; kk++) {
        float4 w = *(float4*)&ows[(CC+kk)*CC + tc*4];
        float4 a = *(float4*)&as_t[kk*XSTRIDE + r0];
        acc[0][0]+=a.x*w.x; acc[0][1]+=a.x*w.y; acc[0][2]+=a.x*w.z; acc[0][3]+=a.x*w.w;
        acc[1][0]+=a.y*w.x; acc[1][1]+=a.y*w.y; acc[1][2]+=a.y*w.z; acc[1][3]+=a.y*w.w;
        acc[2][0]+=a.z*w.x; acc[2][1]+=a.z*w.y; acc[2][2]+=a.z*w.z; acc[2][3]+=a.z*w.w;
        acc[3][0]+=a.w*w.x; acc[3][1]+=a.w*w.y; acc[3][2]+=a.w*w.z; acc[3][3]+=a.w*w.w;
    }
    #pragma unroll
    for (int i = 0; i < 4; i++) {
        #pragma unroll
        for (int j = 0; j < 4; j++) {
            int p = tc*4 + j, r = r0 + i;
            float v = xs_t[p*XSTRIDE + r] + acc[i][j];
            ys_t[p*XSTRIDE + r] = (v > 0.f) ? v : 0.01f * v;
        }
    }
    __syncthreads();
    float acc2[4][4] = {};
    #pragma unroll 16
    for (int kk = 0; kk < CC; kk++) {
        float4 w = *(float4*)&wns[kk*CC + tc*4];
        float4 a = *(float4*)&ys_t[kk*XSTRIDE + r0];
        acc2[0][0]+=a.x*w.x; acc2[0][1]+=a.x*w.y; acc2[0][2]+=a.x*w.z; acc2[0][3]+=a.x*w.w;
        acc2[1][0]+=a.y*w.x; acc2[1][1]+=a.y*w.y; acc2[1][2]+=a.y*w.z; acc2[1][3]+=a.y*w.w;
        acc2[2][0]+=a.z*w.x; acc2[2][1]+=a.z*w.y; acc2[2][2]+=a.z*w.z; acc2[2][3]+=a.z*w.w;
        acc2[3][0]+=a.w*w.x; acc2[3][1]+=a.w*w.y; acc2[3][2]+=a.w*w.z; acc2[3][3]+=a.w*w.w;
    }
    float4 qv = *(float4*)&qs[tc*4];
    float4 kv = *(float4*)&ks_[tc*4];
    #pragma unroll
    for (int i = 0; i < 4; i++) {
        int row = row0 + r0 + i;
        *(float4*)&g_xp2[row*CC + tc*4] = make_float4(acc2[i][0], acc2[i][1], acc2[i][2], acc2[i][3]);
        float pq = acc2[i][0]*qv.x + acc2[i][1]*qv.y + acc2[i][2]*qv.z + acc2[i][3]*qv.w;
        float pk = acc2[i][0]*kv.x + acc2[i][1]*kv.y + acc2[i][2]*kv.z + acc2[i][3]*kv.w;
        #pragma unroll
        for (int o = 8; o; o >>= 1) {
            pq += __shfl_down_sync(0xffffffffu, pq, o, 16);
            pk += __shfl_down_sync(0xffffffffu, pk, o, 16);
        }
        if (tc == 0) { redq[tg*4 + i] = pq; redk[tg*4 + i] = pk; }
    }
    __syncthreads();
    if (tid < 64) {
        g_asrc2[row0 + tid] = redq[tid];
        g_adst2[row0 + tid] = redk[tid];
    }
}

// ---------------- launch 6: final output + re-zero degrees -----------------
__global__ void out2_kernel(const float* __restrict__ ow, const float* __restrict__ ob,
                            float* __restrict__ yout) {
    extern __shared__ __align__(16) float sm[];
    float* ows  = sm;
    float* xs_t = ows + 2*CC*CC;
    float* as_t = xs_t + CC*XSTRIDE;
    __shared__ float obi[CC];
    int tid = threadIdx.x;
    // re-zero degree histogram for the next replay (deterministic: zero before,
    // zero after, every call)
    if (blockIdx.x < 40) {
        int i = blockIdx.x * 256 + tid;
        if (i < NN) g_deg[i] = 0;
    }
    for (int i = tid; i < 2*CC*CC; i += 256) {
        int k = i >> 6, c = i & 63;
        int pk = (k < CC) ? ilv(k) : CC + ilv(k - CC);
        ows[pk*CC + ilv(c)] = ow[i];
    }
    if (tid < CC) obi[tid] = ob[unilv(tid)];
    int row0 = blockIdx.x * 64;
    for (int i = tid*4; i < 64*CC; i += 1024) {
        int r = i >> 6, p0 = i & 63;
        float4 v = *(const float4*)&g_xp2[row0*CC + i];
        xs_t[(p0+0)*XSTRIDE + r] = v.x;
        xs_t[(p0+1)*XSTRIDE + r] = v.y;
        xs_t[(p0+2)*XSTRIDE + r] = v.z;
        xs_t[(p0+3)*XSTRIDE + r] = v.w;
        float4 u = *(const float4*)&g_aggr[row0*CC + i];
        as_t[(p0+0)*XSTRIDE + r] = u.x;
        as_t[(p0+1)*XSTRIDE + r] = u.y;
        as_t[(p0+2)*XSTRIDE + r] = u.z;
        as_t[(p0+3)*XSTRIDE + r] = u.w;
    }
    __syncthreads();
    int tc = tid & 15, tg = tid >> 4;
    int r0 = tg * 4;
    float acc[4][4];
    {
        float4 bv = *(float4*)&obi[tc*4];
        #pragma unroll
        for (int i = 0; i < 4; i++) { acc[i][0]=bv.x; acc[i][1]=bv.y; acc[i][2]=bv.z; acc[i][3]=bv.w; }
    }
    #pragma unroll 16
    for (int kk = 0; kk < CC; kk++) {
        float4 w = *(float4*)&ows[kk*CC + tc*4];
        float4 a = *(float4*)&xs_t[kk*XSTRIDE + r0];
        acc[0][0]+=a.x*w.x; acc[0][1]+=a.x*w.y; acc[0][2]+=a.x*w.z; acc[0][3]+=a.x*w.w;
        acc[1][0]+=a.y*w.x; acc[1][1]+=a.y*w.y; acc[1][2]+=a.y*w.z; acc[1][3]+=a.y*w.w;
        acc[2][0]+=a.z*w.x; acc[2][1]+=a.z*w.y; acc[2][2]+=a.z*w.z; acc[2][3]+=a.z*w.w;
        acc[3][0]+=a.w*w.x; acc[3][1]+=a.w*w.y; acc[3][2]+=a.w*w.z; acc[3][3]+=a.w*w.w;
    }
    #pragma unroll 16
    for (int kk = 0; kk < CC; kk++) {
        float4 w = *(float4*)&ows[(CC+kk)*CC + tc*4];
        float4 a = *(float4*)&as_t[kk*XSTRIDE + r0];
        acc[0][0]+=a.x*w.x; acc[0][1]+=a.x*w.y; acc[0][2]+=a.x*w.z; acc[0][3]+=a.x*w.w;
        acc[1][0]+=a.y*w.x; acc[1][1]+=a.y*w.y; acc[1][2]+=a.y*w.z; acc[1][3]+=a.y*w.w;
        acc[2][0]+=a.z*w.x; acc[2][1]+=a.z*w.y; acc[2][2]+=a.z*w.z; acc[2][3]+=a.z*w.w;
        acc[3][0]+=a.w*w.x; acc[3][1]+=a.w*w.y; acc[3][2]+=a.w*w.z; acc[3][3]+=a.w*w.w;
    }
    #pragma unroll
    for (int i = 0; i < 4; i++) {
        int row = row0 + r0 + i;
        #pragma unroll
        for (int j = 0; j < 4; j++) {
            int p = tc*4 + j;
            float v = xs_t[p*XSTRIDE + (r0+i)] + acc[i][j];
            yout[row*CC + unilv(p)] = (v > 0.f) ? v : 0.01f * v;
        }
    }
}

// ---------------- host orchestration ----------------------------------------
extern "C" void kernel_launch(void* const* d_in, const int* in_sizes, int n_in,
                              void* d_out, int out_size) {
    const float* X   = (const float*)d_in[0];
    const int*   ei  = (const int*)  d_in[1];
    const float* ea  = (const float*)d_in[2];
    const float* wn1 = (const float*)d_in[3];
    const float* we1 = (const float*)d_in[4];
    const float* q1  = (const float*)d_in[5];
    const float* k1  = (const float*)d_in[6];
    const float* aw1 = (const float*)d_in[7];
    const float* ab1 = (const float*)d_in[8];
    const float* ow1 = (const float*)d_in[9];
    const float* ob1 = (const float*)d_in[10];
    const float* wn2 = (const float*)d_in[11];
    const float* we2 = (const float*)d_in[12];
    const float* q2  = (const float*)d_in[13];
    const float* k2  = (const float*)d_in[14];
    const float* aw2 = (const float*)d_in[15];
    const float* ab2 = (const float*)d_in[16];
    const float* ow2 = (const float*)d_in[17];
    const float* ob2 = (const float*)d_in[18];

    float *xp1, *xp2, *asrc1, *adst1, *asrc2, *adst2, *aggr;
    cudaGetSymbolAddress((void**)&xp1,   g_xp1);
    cudaGetSymbolAddress((void**)&xp2,   g_xp2);
    cudaGetSymbolAddress((void**)&asrc1, g_asrc1);
    cudaGetSymbolAddress((void**)&adst1, g_adst1);
    cudaGetSymbolAddress((void**)&asrc2, g_asrc2);
    cudaGetSymbolAddress((void**)&adst2, g_adst2);
    cudaGetSymbolAddress((void**)&aggr,  g_aggr);

    const int MID_SMEM = (2*CC*CC + CC*CC + 3*CC*XSTRIDE) * 4;
    const int OUT_SMEM = (2*CC*CC + 2*CC*XSTRIDE) * 4;
    static bool attr_done = false;
    if (!attr_done) {
        cudaFuncSetAttribute(mid_kernel,  cudaFuncAttributeMaxDynamicSharedMemorySize, MID_SMEM);
        cudaFuncSetAttribute(out2_kernel, cudaFuncAttributeMaxDynamicSharedMemorySize, OUT_SMEM);
        attr_done = true;
    }

    prep_count_kernel<<<625, 256>>>(ei, q1, k1, aw1, ab1, we1, q2, k2, aw2, ab2, we2); // 0
    scan_kernel<<<1, 1024>>>();                                                        // 1
    xform1_scatter_kernel<<<625, 256>>>(X, wn1, ei, ea);                               // 2
    aggr_kernel<<<NN/8, 256>>>(xp1, asrc1, adst1, aggr, we1, ea, 0);                   // 3 <- probe
    mid_kernel<<<NR/64, 256, MID_SMEM>>>(ow1, ob1, wn2);                               // 4
    aggr_kernel<<<NN/8, 256>>>(xp2, asrc2, adst2, aggr, we2, ea, 1);                   // 5
    out2_kernel<<<NR/64, 256, OUT_SMEM>>>(ow2, ob2, (float*)d_out);                    // 6
}

// round 8
// speedup vs baseline: 1.9423x; 1.1052x over previous
#include <cuda_runtime.h>
#include <math_constants.h>

#define NN 10000
#define BB 4
#define EE 160000
#define CC 64
#define CE 16
#define NR (NN*BB)          // 40000 rows
#define XSTRIDE 68          // padded row stride for transposed activation tiles

// INTERLEAVED channel layout for node tensors: channel c of row r lives at
// [r*64 + ilv(c)], ilv(c) = (c&31)*2 + (c>>5); unilv(p) = (p>>1) + (p&1)*32.
__device__ float  g_xp1[NR*CC];
__device__ float  g_xp2[NR*CC];
__device__ float  g_aggr[NR*CC];
__device__ float  g_asrc1[NR], g_adst1[NR];
__device__ float  g_asrc2[NR], g_adst2[NR];
__device__ float  g_qaw[2][CC], g_kaw[2][CC], g_wea[2][CE];
__device__ float  g_abv[2];
__device__ float2 g_esc[EE];         // per-edge attention scalar, both layers
__device__ int  g_deg[NN];           // zeroed at END of each run (and statically)
__device__ int  g_off[NN+1];
__device__ int  g_cur[NN];
__device__ int2 g_lst[EE];           // {edge id, src node}

__device__ __forceinline__ float sigmoidf(float x) {
    return 1.0f / (1.0f + __expf(-x));
}
__device__ __forceinline__ int ilv(int c)   { return (c & 31) * 2 + (c >> 5); }
__device__ __forceinline__ int unilv(int p) { return (p >> 1) + (p & 1) * 32; }

// ---------------- launch 0: fold attention weights + degree count ----------
__global__ void prep_count_kernel(const int* __restrict__ ei,
                                  const float* q1, const float* k1, const float* aw1,
                                  const float* ab1, const float* we1,
                                  const float* q2, const float* k2, const float* aw2,
                                  const float* ab2, const float* we2) {
    int tid = threadIdx.x;
    if (blockIdx.x < 2) {
        int layer = blockIdx.x;
        const float* q  = layer ? q2  : q1;
        const float* k  = layer ? k2  : k1;
        const float* aw = layer ? aw2 : aw1;
        const float* ab = layer ? ab2 : ab1;
        const float* we = layer ? we2 : we1;
        int w = tid >> 5, lane = tid & 31;
        float awq_lo = aw[lane],        awq_hi = aw[32 + lane];
        float awk_lo = aw[64 + lane],   awk_hi = aw[96 + lane];
        float aw3_lo = aw[128 + lane],  aw3_hi = aw[160 + lane];
        #pragma unroll
        for (int i = 0; i < 8; i++) {
            int row = w * 8 + i;
            float sq = q[row*CC + lane] * awq_lo + q[row*CC + 32 + lane] * awq_hi;
            float sk = k[row*CC + lane] * awk_lo + k[row*CC + 32 + lane] * awk_hi;
            #pragma unroll
            for (int o = 16; o; o >>= 1) {
                sq += __shfl_down_sync(0xffffffffu, sq, o);
                sk += __shfl_down_sync(0xffffffffu, sk, o);
            }
            if (lane == 0) { g_qaw[layer][row] = sq; g_kaw[layer][row] = sk; }
        }
        #pragma unroll
        for (int i = 0; i < 2; i++) {
            int row = w * 2 + i;
            float s = we[row*CC + lane] * aw3_lo + we[row*CC + 32 + lane] * aw3_hi;
            #pragma unroll
            for (int o = 16; o; o >>= 1) s += __shfl_down_sync(0xffffffffu, s, o);
            if (lane == 0) g_wea[layer][row] = s;
        }
        if (tid == 0) g_abv[layer] = ab[0];
    }
    int e = blockIdx.x * 256 + tid;   // 625*256 = 160000 exactly
    atomicAdd(&g_deg[ei[EE + e]], 1);
}

// ---------------- launch 1: exclusive scan -> g_off / g_cur ----------------
__global__ void scan_kernel() {
    __shared__ int s[1024];
    const int CH = (NN + 1023) / 1024;
    int t = threadIdx.x;
    int base = t * CH;
    int local[CH];
    int sum = 0;
    #pragma unroll
    for (int i = 0; i < CH; i++) {
        local[i] = sum;
        if (base + i < NN) sum += g_deg[base + i];
    }
    s[t] = sum;
    __syncthreads();
    for (int off = 1; off < 1024; off <<= 1) {
        int v = (t >= off) ? s[t - off] : 0;
        __syncthreads();
        s[t] += v;
        __syncthreads();
    }
    int excl = (t == 0) ? 0 : s[t - 1];
    #pragma unroll
    for (int i = 0; i < CH; i++) {
        if (base + i < NN) {
            int o = excl + local[i];
            g_off[base + i] = o;
            g_cur[base + i] = o;
        }
    }
    if (t == 1023) g_off[NN] = s[1023];
}

// ---------------- launch 2: xform1 GEMM + CSR scatter + escal (fused) ------
__global__ void xform1_scatter_kernel(const float* __restrict__ x,
                                      const float* __restrict__ wn,
                                      const int* __restrict__ ei,
                                      const float* __restrict__ eattr) {
    __shared__ __align__(16) float ws[CC*CC];         // [k][interleaved c]
    __shared__ __align__(16) float xs_t[CC*XSTRIDE];  // [k][row]
    __shared__ float qs[CC], ks_[CC];
    __shared__ float redq[64], redk[64];
    __shared__ float w1[CE], w2[CE];
    __shared__ float ab0, ab1;
    int tid = threadIdx.x;
    for (int i = tid; i < CC*CC; i += 256) {
        int kk = i >> 6, c = i & 63;
        ws[kk*CC + ilv(c)] = wn[i];
    }
    if (tid < CC) { qs[tid] = g_qaw[0][unilv(tid)]; ks_[tid] = g_kaw[0][unilv(tid)]; }
    if (tid >= 64 && tid < 64 + CE) { w1[tid-64] = g_wea[0][tid-64]; w2[tid-64] = g_wea[1][tid-64]; }
    if (tid == 127) { ab0 = g_abv[0]; ab1 = g_abv[1]; }
    int row0 = blockIdx.x * 64;
    for (int i = tid*4; i < 64*CC; i += 1024) {
        float4 v = *(const float4*)&x[row0*CC + i];
        int r = i >> 6, c0 = i & 63;
        xs_t[(c0+0)*XSTRIDE + r] = v.x;
        xs_t[(c0+1)*XSTRIDE + r] = v.y;
        xs_t[(c0+2)*XSTRIDE + r] = v.z;
        xs_t[(c0+3)*XSTRIDE + r] = v.w;
    }
    __syncthreads();
    // ---- scatter + escal for this block's 256 edges ----
    {
        int e = blockIdx.x * 256 + tid;
        int src = ei[e];
        int dst = ei[EE + e];
        int pos = atomicAdd(&g_cur[dst], 1);
        g_lst[pos] = make_int2(e, src);
        const float4* p = (const float4*)(eattr + (size_t)e * CE);
        float4 A = p[0], B = p[1], C = p[2], D = p[3];
        float a[16] = {A.x,A.y,A.z,A.w, B.x,B.y,B.z,B.w, C.x,C.y,C.z,C.w, D.x,D.y,D.z,D.w};
        float s1 = 0.f, s2 = 0.f;
        #pragma unroll
        for (int j = 0; j < CE; j++) { s1 += a[j]*w1[j]; s2 += a[j]*w2[j]; }
        g_esc[e] = make_float2(s1 + ab0, s2 + ab1);
    }
    // ---- register-tiled GEMM: 64 rows x 64 cols ----
    int tc = tid & 15, tg = tid >> 4;
    int r0 = tg * 4;
    float acc[4][4] = {};
    #pragma unroll 16
    for (int kk = 0; kk < CC; kk++) {
        float4 w = *(float4*)&ws[kk*CC + tc*4];
        float4 a = *(float4*)&xs_t[kk*XSTRIDE + r0];
        acc[0][0]+=a.x*w.x; acc[0][1]+=a.x*w.y; acc[0][2]+=a.x*w.z; acc[0][3]+=a.x*w.w;
        acc[1][0]+=a.y*w.x; acc[1][1]+=a.y*w.y; acc[1][2]+=a.y*w.z; acc[1][3]+=a.y*w.w;
        acc[2][0]+=a.z*w.x; acc[2][1]+=a.z*w.y; acc[2][2]+=a.z*w.z; acc[2][3]+=a.z*w.w;
        acc[3][0]+=a.w*w.x; acc[3][1]+=a.w*w.y; acc[3][2]+=a.w*w.z; acc[3][3]+=a.w*w.w;
    }
    float4 qv = *(float4*)&qs[tc*4];
    float4 kv = *(float4*)&ks_[tc*4];
    #pragma unroll
    for (int i = 0; i < 4; i++) {
        int row = row0 + r0 + i;
        *(float4*)&g_xp1[row*CC + tc*4] = make_float4(acc[i][0], acc[i][1], acc[i][2], acc[i][3]);
        float pq = acc[i][0]*qv.x + acc[i][1]*qv.y + acc[i][2]*qv.z + acc[i][3]*qv.w;
        float pk = acc[i][0]*kv.x + acc[i][1]*kv.y + acc[i][2]*kv.z + acc[i][3]*kv.w;
        #pragma unroll
        for (int o = 8; o; o >>= 1) {
            pq += __shfl_down_sync(0xffffffffu, pq, o, 16);
            pk += __shfl_down_sync(0xffffffffu, pk, o, 16);
        }
        if (tc == 0) { redq[tg*4 + i] = pq; redk[tg*4 + i] = pk; }
    }
    __syncthreads();
    if (tid < 64) {
        g_asrc1[row0 + tid] = redq[tid];
        g_adst1[row0 + tid] = redk[tid];
    }
}

// ---------------- launch 3 (PROBE) / 5: segment max, 2 warps per node ------
// block = 256 = 8 warps = 4 nodes x 2 half-warps; halves combine via smem fmax
__global__ void aggr_kernel(const float* __restrict__ xp, const float* __restrict__ asrcp,
                            const float* __restrict__ adstp, float* __restrict__ aggrp,
                            const float* __restrict__ we, const float* __restrict__ eattr,
                            int layer) {
    __shared__ __align__(8) float2 wsh[CE*32];       // gate weights [j][lane], 4KB
    __shared__ float2 part[4][BB][32];               // half-1 partials, 4KB
    int tid = threadIdx.x;
    int lane = tid & 31;
    int w = tid >> 5;
    int nloc = w >> 1, half = w & 1;
    int lb = lane & 3;
    for (int i = tid; i < CE*32; i += 256) {
        int j = i >> 5, l = i & 31;
        wsh[i] = make_float2(we[j*CC + l], we[j*CC + 32 + l]);
    }
    __syncthreads();
    int n = blockIdx.x * 4 + nloc;
    int beg0 = g_off[n], end0 = g_off[n+1];
    int mid = beg0 + ((end0 - beg0) >> 1);
    int beg = half ? mid : beg0;
    int end = half ? end0 : mid;
    float ad_l = adstp[n*4 + lb];
    float mx0[BB], mx1[BB];
    #pragma unroll
    for (int b = 0; b < BB; b++) { mx0[b] = -CUDART_INF_F; mx1[b] = -CUDART_INF_F; }
    int2 nx = (beg < end) ? __ldg(&g_lst[beg]) : make_int2(0, 0);
    for (int i = beg; i < end; i++) {
        int e = nx.x, src = nx.y;
        if (i + 1 < end) nx = __ldg(&g_lst[i+1]);
        const float4* p4 = (const float4*)(eattr + (size_t)e * CE);
        float4 A = p4[0], B = p4[1], Cv = p4[2], D = p4[3];
        float2 e2 = __ldg(&g_esc[e]);
        float esc = layer ? e2.y : e2.x;
        float as_l = __ldg(&asrcp[src*4 + lb]);
        float att_l = sigmoidf(as_l + ad_l + esc);
        float attv[BB];
        #pragma unroll
        for (int b = 0; b < BB; b++) attv[b] = __shfl_sync(0xffffffffu, att_l, b, 4);
        float av[16] = {A.x,A.y,A.z,A.w, B.x,B.y,B.z,B.w, Cv.x,Cv.y,Cv.z,Cv.w, D.x,D.y,D.z,D.w};
        float gx = 0.f, gy = 0.f, hx = 0.f, hy = 0.f;
        #pragma unroll
        for (int j = 0; j < CE; j += 2) {
            float2 w0 = wsh[(j  )*32 + lane];
            float2 w1 = wsh[(j+1)*32 + lane];
            gx += av[j]  * w0.x;  gy += av[j]  * w0.y;
            hx += av[j+1]* w1.x;  hy += av[j+1]* w1.y;
        }
        float gA = sigmoidf(gx + hx);
        float gB = sigmoidf(gy + hy);
        #pragma unroll
        for (int b = 0; b < BB; b++) {
            float2 x = *(const float2*)&xp[(src*BB + b)*CC + lane*2];
            mx0[b] = fmaxf(mx0[b], attv[b] * x.x * gA);
            mx1[b] = fmaxf(mx1[b], attv[b] * x.y * gB);
        }
    }
    if (half == 1) {
        #pragma unroll
        for (int b = 0; b < BB; b++) part[nloc][b][lane] = make_float2(mx0[b], mx1[b]);
    }
    __syncthreads();
    if (half == 0) {
        bool empty = (beg0 == end0);
        #pragma unroll
        for (int b = 0; b < BB; b++) {
            float2 p1 = part[nloc][b][lane];
            float2 o = empty ? make_float2(0.f, 0.f)
                             : make_float2(fmaxf(mx0[b], p1.x), fmaxf(mx1[b], p1.y));
            *(float2*)&aggrp[(n*BB + b)*CC + lane*2] = o;
        }
    }
}

// ---------------- launch 4: fused layer1 output + layer2 transform ---------
__global__ void mid_kernel(const float* __restrict__ ow, const float* __restrict__ ob,
                           const float* __restrict__ wn2) {
    extern __shared__ __align__(16) float sm[];
    float* ows  = sm;
    float* wns  = ows + 2*CC*CC;
    float* xs_t = wns + CC*CC;
    float* as_t = xs_t + CC*XSTRIDE;
    float* ys_t = as_t + CC*XSTRIDE;
    __shared__ float obi[CC], qs[CC], ks_[CC];
    __shared__ float redq[64], redk[64];
    int tid = threadIdx.x;
    for (int i = tid; i < 2*CC*CC; i += 256) {
        int k = i >> 6, c = i & 63;
        int pk = (k < CC) ? ilv(k) : CC + ilv(k - CC);
        ows[pk*CC + ilv(c)] = ow[i];
    }
    for (int i = tid; i < CC*CC; i += 256) {
        int k = i >> 6, c = i & 63;
        wns[ilv(k)*CC + ilv(c)] = wn2[i];
    }
    if (tid < CC) {
        int c = unilv(tid);
        obi[tid] = ob[c];
        qs[tid]  = g_qaw[1][c];
        ks_[tid] = g_kaw[1][c];
    }
    int row0 = blockIdx.x * 64;
    for (int i = tid*4; i < 64*CC; i += 1024) {
        int r = i >> 6, p0 = i & 63;
        float4 v = *(const float4*)&g_xp1[row0*CC + i];
        xs_t[(p0+0)*XSTRIDE + r] = v.x;
        xs_t[(p0+1)*XSTRIDE + r] = v.y;
        xs_t[(p0+2)*XSTRIDE + r] = v.z;
        xs_t[(p0+3)*XSTRIDE + r] = v.w;
        float4 u = *(const float4*)&g_aggr[row0*CC + i];
        as_t[(p0+0)*XSTRIDE + r] = u.x;
        as_t[(p0+1)*XSTRIDE + r] = u.y;
        as_t[(p0+2)*XSTRIDE + r] = u.z;
        as_t[(p0+3)*XSTRIDE + r] = u.w;
    }
    __syncthreads();
    int tc = tid & 15, tg = tid >> 4;
    int r0 = tg * 4;
    float acc[4][4];
    {
        float4 bv = *(float4*)&obi[tc*4];
        #pragma unroll
        for (int i = 0; i < 4; i++) { acc[i][0]=bv.x; acc[i][1]=bv.y; acc[i][2]=bv.z; acc[i][3]=bv.w; }
    }
    #pragma unroll 16
    for (int kk = 0; kk < CC; kk++) {
        float4 w = *(float4*)&ows[kk*CC + tc*4];
        float4 a = *(float4*)&xs_t[kk*XSTRIDE + r0];
        acc[0][0]+=a.x*w.x; acc[0][1]+=a.x*w.y; acc[0][2]+=a.x*w.z; acc[0][3]+=a.x*w.w;
        acc[1][0]+=a.y*w.x; acc[1][1]+=a.y*w.y; acc[1][2]+=a.y*w.z; acc[1][3]+=a.y*w.w;
        acc[2][0]+=a.z*w.x; acc[2][1]+=a.z*w.y; acc[2][2]+=a.z*w.z; acc[2][3]+=a.z*w.w;
        acc[3][0]+=a.w*w.x; acc[3][1]+=a.w*w.y; acc[3][2]+=a.w*w.z; acc[3][3]+=a.w*w.w;
    }
    #pragma unroll 16
    for (int kk = 0; kk < CC; kk++) {
        float4 w = *(float4*)&ows[(CC+kk)*CC + tc*4];
        float4 a = *(float4*)&as_t[kk*XSTRIDE + r0];
        acc[0][0]+=a.x*w.x; acc[0][1]+=a.x*w.y; acc[0][2]+=a.x*w.z; acc[0][3]+=a.x*w.w;
        acc[1][0]+=a.y*w.x; acc[1][1]+=a.y*w.y; acc[1][2]+=a.y*w.z; acc[1][3]+=a.y*w.w;
        acc[2][0]+=a.z*w.x; acc[2][1]+=a.z*w.y; acc[2][2]+=a.z*w.z; acc[2][3]+=a.z*w.w;
        acc[3][0]+=a.w*w.x; acc[3][1]+=a.w*w.y; acc[3][2]+=a.w*w.z; acc[3][3]+=a.w*w.w;
    }
    #pragma unroll
    for (int i = 0; i < 4; i++) {
        #pragma unroll
        for (int j = 0; j < 4; j++) {
            int p = tc*4 + j, r = r0 + i;
            float v = xs_t[p*XSTRIDE + r] + acc[i][j];
            ys_t[p*XSTRIDE + r] = (v > 0.f) ? v : 0.01f * v;
        }
    }
    __syncthreads();
    float acc2[4][4] = {};
    #pragma unroll 16
    for (int kk = 0; kk < CC; kk++) {
        float4 w = *(float4*)&wns[kk*CC + tc*4];
        float4 a = *(float4*)&ys_t[kk*XSTRIDE + r0];
        acc2[0][0]+=a.x*w.x; acc2[0][1]+=a.x*w.y; acc2[0][2]+=a.x*w.z; acc2[0][3]+=a.x*w.w;
        acc2[1][0]+=a.y*w.x; acc2[1][1]+=a.y*w.y; acc2[1][2]+=a.y*w.z; acc2[1][3]+=a.y*w.w;
        acc2[2][0]+=a.z*w.x; acc2[2][1]+=a.z*w.y; acc2[2][2]+=a.z*w.z; acc2[2][3]+=a.z*w.w;
        acc2[3][0]+=a.w*w.x; acc2[3][1]+=a.w*w.y; acc2[3][2]+=a.w*w.z; acc2[3][3]+=a.w*w.w;
    }
    float4 qv = *(float4*)&qs[tc*4];
    float4 kv = *(float4*)&ks_[tc*4];
    #pragma unroll
    for (int i = 0; i < 4; i++) {
        int row = row0 + r0 + i;
        *(float4*)&g_xp2[row*CC + tc*4] = make_float4(acc2[i][0], acc2[i][1], acc2[i][2], acc2[i][3]);
        float pq = acc2[i][0]*qv.x + acc2[i][1]*qv.y + acc2[i][2]*qv.z + acc2[i][3]*qv.w;
        float pk = acc2[i][0]*kv.x + acc2[i][1]*kv.y + acc2[i][2]*kv.z + acc2[i][3]*kv.w;
        #pragma unroll
        for (int o = 8; o; o >>= 1) {
            pq += __shfl_down_sync(0xffffffffu, pq, o, 16);
            pk += __shfl_down_sync(0xffffffffu, pk, o, 16);
        }
        if (tc == 0) { redq[tg*4 + i] = pq; redk[tg*4 + i] = pk; }
    }
    __syncthreads();
    if (tid < 64) {
        g_asrc2[row0 + tid] = redq[tid];
        g_adst2[row0 + tid] = redk[tid];
    }
}

// ---------------- launch 6: final output + re-zero degrees -----------------
__global__ void out2_kernel(const float* __restrict__ ow, const float* __restrict__ ob,
                            float* __restrict__ yout) {
    extern __shared__ __align__(16) float sm[];
    float* ows  = sm;
    float* xs_t = ows + 2*CC*CC;
    float* as_t = xs_t + CC*XSTRIDE;
    __shared__ float obi[CC];
    int tid = threadIdx.x;
    if (blockIdx.x < 40) {
        int i = blockIdx.x * 256 + tid;
        if (i < NN) g_deg[i] = 0;
    }
    for (int i = tid; i < 2*CC*CC; i += 256) {
        int k = i >> 6, c = i & 63;
        int pk = (k < CC) ? ilv(k) : CC + ilv(k - CC);
        ows[pk*CC + ilv(c)] = ow[i];
    }
    if (tid < CC) obi[tid] = ob[unilv(tid)];
    int row0 = blockIdx.x * 64;
    for (int i = tid*4; i < 64*CC; i += 1024) {
        int r = i >> 6, p0 = i & 63;
        float4 v = *(const float4*)&g_xp2[row0*CC + i];
        xs_t[(p0+0)*XSTRIDE + r] = v.x;
        xs_t[(p0+1)*XSTRIDE + r] = v.y;
        xs_t[(p0+2)*XSTRIDE + r] = v.z;
        xs_t[(p0+3)*XSTRIDE + r] = v.w;
        float4 u = *(const float4*)&g_aggr[row0*CC + i];
        as_t[(p0+0)*XSTRIDE + r] = u.x;
        as_t[(p0+1)*XSTRIDE + r] = u.y;
        as_t[(p0+2)*XSTRIDE + r] = u.z;
        as_t[(p0+3)*XSTRIDE + r] = u.w;
    }
    __syncthreads();
    int tc = tid & 15, tg = tid >> 4;
    int r0 = tg * 4;
    float acc[4][4];
    {
        float4 bv = *(float4*)&obi[tc*4];
        #pragma unroll
        for (int i = 0; i < 4; i++) { acc[i][0]=bv.x; acc[i][1]=bv.y; acc[i][2]=bv.z; acc[i][3]=bv.w; }
    }
    #pragma unroll 16
    for (int kk = 0; kk < CC; kk++) {
        float4 w = *(float4*)&ows[kk*CC + tc*4];
        float4 a = *(float4*)&xs_t[kk*XSTRIDE + r0];
        acc[0][0]+=a.x*w.x; acc[0][1]+=a.x*w.y; acc[0][2]+=a.x*w.z; acc[0][3]+=a.x*w.w;
        acc[1][0]+=a.y*w.x; acc[1][1]+=a.y*w.y; acc[1][2]+=a.y*w.z; acc[1][3]+=a.y*w.w;
        acc[2][0]+=a.z*w.x; acc[2][1]+=a.z*w.y; acc[2][2]+=a.z*w.z; acc[2][3]+=a.z*w.w;
        acc[3][0]+=a.w*w.x; acc[3][1]+=a.w*w.y; acc[3][2]+=a.w*w.z; acc[3][3]+=a.w*w.w;
    }
    #pragma unroll 16
    for (int kk = 0; kk < CC; kk++) {
        float4 w = *(float4*)&ows[(CC+kk)*CC + tc*4];
        float4 a = *(float4*)&as_t[kk*XSTRIDE + r0];
        acc[0][0]+=a.x*w.x; acc[0][1]+=a.x*w.y; acc[0][2]+=a.x*w.z; acc[0][3]+=a.x*w.w;
        acc[1][0]+=a.y*w.x; acc[1][1]+=a.y*w.y; acc[1][2]+=a.y*w.z; acc[1][3]+=a.y*w.w;
        acc[2][0]+=a.z*w.x; acc[2][1]+=a.z*w.y; acc[2][2]+=a.z*w.z; acc[2][3]+=a.z*w.w;
        acc[3][0]+=a.w*w.x; acc[3][1]+=a.w*w.y; acc[3][2]+=a.w*w.z; acc[3][3]+=a.w*w.w;
    }
    #pragma unroll
    for (int i = 0; i < 4; i++) {
        int row = row0 + r0 + i;
        #pragma unroll
        for (int j = 0; j < 4; j++) {
            int p = tc*4 + j;
            float v = xs_t[p*XSTRIDE + (r0+i)] + acc[i][j];
            yout[row*CC + unilv(p)] = (v > 0.f) ? v : 0.01f * v;
        }
    }
}

// ---------------- host orchestration ----------------------------------------
extern "C" void kernel_launch(void* const* d_in, const int* in_sizes, int n_in,
                              void* d_out, int out_size) {
    const float* X   = (const float*)d_in[0];
    const int*   ei  = (const int*)  d_in[1];
    const float* ea  = (const float*)d_in[2];
    const float* wn1 = (const float*)d_in[3];
    const float* we1 = (const float*)d_in[4];
    const float* q1  = (const float*)d_in[5];
    const float* k1  = (const float*)d_in[6];
    const float* aw1 = (const float*)d_in[7];
    const float* ab1 = (const float*)d_in[8];
    const float* ow1 = (const float*)d_in[9];
    const float* ob1 = (const float*)d_in[10];
    const float* wn2 = (const float*)d_in[11];
    const float* we2 = (const float*)d_in[12];
    const float* q2  = (const float*)d_in[13];
    const float* k2  = (const float*)d_in[14];
    const float* aw2 = (const float*)d_in[15];
    const float* ab2 = (const float*)d_in[16];
    const float* ow2 = (const float*)d_in[17];
    const float* ob2 = (const float*)d_in[18];

    float *xp1, *xp2, *asrc1, *adst1, *asrc2, *adst2, *aggr;
    cudaGetSymbolAddress((void**)&xp1,   g_xp1);
    cudaGetSymbolAddress((void**)&xp2,   g_xp2);
    cudaGetSymbolAddress((void**)&asrc1, g_asrc1);
    cudaGetSymbolAddress((void**)&adst1, g_adst1);
    cudaGetSymbolAddress((void**)&asrc2, g_asrc2);
    cudaGetSymbolAddress((void**)&adst2, g_adst2);
    cudaGetSymbolAddress((void**)&aggr,  g_aggr);

    const int MID_SMEM = (2*CC*CC + CC*CC + 3*CC*XSTRIDE) * 4;
    const int OUT_SMEM = (2*CC*CC + 2*CC*XSTRIDE) * 4;
    static bool attr_done = false;
    if (!attr_done) {
        cudaFuncSetAttribute(mid_kernel,  cudaFuncAttributeMaxDynamicSharedMemorySize, MID_SMEM);
        cudaFuncSetAttribute(out2_kernel, cudaFuncAttributeMaxDynamicSharedMemorySize, OUT_SMEM);
        attr_done = true;
    }

    prep_count_kernel<<<625, 256>>>(ei, q1, k1, aw1, ab1, we1, q2, k2, aw2, ab2, we2); // 0
    scan_kernel<<<1, 1024>>>();                                                        // 1
    xform1_scatter_kernel<<<625, 256>>>(X, wn1, ei, ea);                               // 2
    aggr_kernel<<<NN/4, 256>>>(xp1, asrc1, adst1, aggr, we1, ea, 0);                   // 3 <- probe
    mid_kernel<<<NR/64, 256, MID_SMEM>>>(ow1, ob1, wn2);                               // 4
    aggr_kernel<<<NN/4, 256>>>(xp2, asrc2, adst2, aggr, we2, ea, 1);                   // 5
    out2_kernel<<<NR/64, 256, OUT_SMEM>>>(ow2, ob2, (float*)d_out);                    // 6
}